// round 1
// baseline (speedup 1.0000x reference)
#include <cuda_runtime.h>
#include <math.h>

// Problem constants
#define Bsz 4
#define Cc  64
#define Nn  4096
#define Dd  64
#define HIDD 256
#define EPSBN 1e-5f

// ---------------- scratch (__device__ globals; no allocation) ----------------
__device__ float gFl [Bsz*Cc*Nn];     // Fs+Ff, channel-major [B][C][N]
__device__ float gQT [Bsz*Nn*128];    // [scale*q1 | -scale*lam*q2], token-major [B][N][128]
__device__ float gKT [Bsz*Nn*128];    // [k1 | k2]
__device__ float gV  [Bsz*Nn*Dd];     // v, token-major
__device__ float gAtt[Bsz*Nn*Dd];     // attention output, token-major
__device__ float gO  [Bsz*Nn*Cc];     // Wproj @ att, token-major
__device__ float gY  [Bsz*Cc*Nn];     // FFN output, channel-major
__device__ float gStats[2*Cc];        // mean[64], invstd[64]

// ---------------- K1: Fl = Fs + Ff ----------------
__global__ void add_kernel(const float* __restrict__ a, const float* __restrict__ b) {
    int i = blockIdx.x * blockDim.x + threadIdx.x;
    gFl[i] = a[i] + b[i];
}

// ---------------- K2: 5 input projections (1x1 convs) ----------------
// Block: 64 tokens of one batch. q/k folded with scale and lambda.
__global__ void __launch_bounds__(256) proj_kernel(
    const float* __restrict__ Wq1, const float* __restrict__ Wk1,
    const float* __restrict__ Wq2, const float* __restrict__ Wk2,
    const float* __restrict__ Wv,  const float* __restrict__ lam_p)
{
    __shared__ float xs[64*65];   // x tile [c][n], padded
    __shared__ float wo[64*65];   // weight buffer, then output-transpose buffer

    int b  = blockIdx.y;
    int n0 = blockIdx.x << 6;
    int t  = threadIdx.x;

    for (int idx = t; idx < 4096; idx += 256) {
        int c = idx >> 6, nn = idx & 63;
        xs[c*65 + nn] = gFl[((b<<6) + c)*Nn + n0 + nn];
    }
    float lam = __ldg(lam_p);
    const float* Ws[5] = {Wq1, Wk1, Wq2, Wk2, Wv};
    const float  scl[5] = {0.125f, 1.0f, -0.125f*lam, 1.0f, 1.0f};

    int n = t & 63, g = t >> 6;

    for (int m = 0; m < 5; m++) {
        __syncthreads();
        for (int idx = t; idx < 4096; idx += 256) wo[idx] = Ws[m][idx];  // W[d][c]
        __syncthreads();

        float acc[16];
        #pragma unroll
        for (int i = 0; i < 16; i++) acc[i] = 0.f;

        for (int c = 0; c < 64; c++) {
            float xv = xs[c*65 + n];
            #pragma unroll
            for (int i = 0; i < 16; i++)
                acc[i] = fmaf(wo[(g*16 + i)*64 + c], xv, acc[i]);
        }
        __syncthreads();
        float s = scl[m];
        #pragma unroll
        for (int i = 0; i < 16; i++) wo[n*65 + g*16 + i] = acc[i] * s;
        __syncthreads();

        float* dst; int stride, off;
        if      (m == 0) { dst = gQT; stride = 128; off = 0;  }
        else if (m == 1) { dst = gKT; stride = 128; off = 0;  }
        else if (m == 2) { dst = gQT; stride = 128; off = 64; }
        else if (m == 3) { dst = gKT; stride = 128; off = 64; }
        else             { dst = gV;  stride = 64;  off = 0;  }

        for (int idx = t; idx < 4096; idx += 256) {
            int nn = idx >> 6, d = idx & 63;
            dst[(b*Nn + n0 + nn)*stride + off + d] = wo[nn*65 + d];
        }
    }
}

// ---------------- K3: flash attention, fp32 SIMT ----------------
// Block: 64 queries. 256 threads as 16x16 (tq,tk); thread owns 4 queries x 4 keys
// in QK, and 4 queries x 4 v-dims in PV. XOR-swizzled K/Q tiles for conflict-free
// strided float4 reads.
#define FLASH_SMEM_F4 (2048 + 2048 + 1024 + 64*17)   // qs, ks, vs, ps (float4 units)

__global__ void __launch_bounds__(256) flash_kernel()
{
    extern __shared__ float4 sm4[];
    float4* qs = sm4;           // [64 rows][32 chunks] swizzled
    float4* ks = sm4 + 2048;    // [64][32] swizzled
    float4* vs = sm4 + 4096;    // [64 keys][16 chunks]
    float4* ps = sm4 + 5120;    // [64 q][17 chunks] (stride 68 floats)
    float*  psf = (float*)ps;

    int b  = blockIdx.y;
    int q0 = blockIdx.x << 6;
    int t  = threadIdx.x;
    int tq = t >> 4, tk = t & 15;

    const float4* QT = (const float4*)gQT + (b*Nn + q0) * 32;
    const float4* KT = (const float4*)gKT + b*Nn * 32;
    const float4* V4 = (const float4*)gV  + b*Nn * 16;

    // load Q tile swizzled
    for (int idx = t; idx < 2048; idx += 256) {
        int r = idx >> 5, c = idx & 31;
        qs[r*32 + (c ^ (r & 31))] = QT[r*32 + c];
    }

    float m_i[4], l_i[4], acc[4][4];
    #pragma unroll
    for (int i = 0; i < 4; i++) {
        m_i[i] = -1e30f; l_i[i] = 0.f;
        #pragma unroll
        for (int j = 0; j < 4; j++) acc[i][j] = 0.f;
    }

    int rq[4], rk[4];
    #pragma unroll
    for (int i = 0; i < 4; i++) { rq[i] = 4*tq + i; rk[i] = 4*tk + i; }

    for (int kt0 = 0; kt0 < Nn; kt0 += 64) {
        __syncthreads();
        for (int idx = t; idx < 2048; idx += 256) {
            int r = idx >> 5, c = idx & 31;
            ks[r*32 + (c ^ (r & 31))] = KT[(kt0 + r)*32 + c];
        }
        for (int idx = t; idx < 1024; idx += 256)
            vs[idx] = V4[kt0*16 + idx];
        __syncthreads();

        // ---- QK: s[4q][4k] over 128 dims ----
        float s[4][4];
        #pragma unroll
        for (int i = 0; i < 4; i++)
            #pragma unroll
            for (int j = 0; j < 4; j++) s[i][j] = 0.f;

        for (int e4 = 0; e4 < 32; e4++) {
            float4 qf[4], kf[4];
            #pragma unroll
            for (int i = 0; i < 4; i++) qf[i] = qs[rq[i]*32 + (e4 ^ (rq[i] & 31))];
            #pragma unroll
            for (int j = 0; j < 4; j++) kf[j] = ks[rk[j]*32 + (e4 ^ (rk[j] & 31))];
            #pragma unroll
            for (int i = 0; i < 4; i++)
                #pragma unroll
                for (int j = 0; j < 4; j++) {
                    s[i][j] = fmaf(qf[i].x, kf[j].x, s[i][j]);
                    s[i][j] = fmaf(qf[i].y, kf[j].y, s[i][j]);
                    s[i][j] = fmaf(qf[i].z, kf[j].z, s[i][j]);
                    s[i][j] = fmaf(qf[i].w, kf[j].w, s[i][j]);
                }
        }

        // ---- online softmax (row reduce over 16 tk lanes, shfl within half-warp) ----
        #pragma unroll
        for (int i = 0; i < 4; i++) {
            float mx = fmaxf(fmaxf(s[i][0], s[i][1]), fmaxf(s[i][2], s[i][3]));
            #pragma unroll
            for (int d = 1; d < 16; d <<= 1)
                mx = fmaxf(mx, __shfl_xor_sync(0xffffffffu, mx, d));
            float mnew = fmaxf(m_i[i], mx);
            float corr = __expf(m_i[i] - mnew);
            m_i[i] = mnew;
            float4 p;
            p.x = __expf(s[i][0] - mnew);
            p.y = __expf(s[i][1] - mnew);
            p.z = __expf(s[i][2] - mnew);
            p.w = __expf(s[i][3] - mnew);
            float rs = (p.x + p.y) + (p.z + p.w);
            #pragma unroll
            for (int d = 1; d < 16; d <<= 1)
                rs += __shfl_xor_sync(0xffffffffu, rs, d);
            l_i[i] = l_i[i]*corr + rs;
            #pragma unroll
            for (int j = 0; j < 4; j++) acc[i][j] *= corr;
            ps[rq[i]*17 + tk] = p;   // row produced & consumed within same half-warp
        }
        __syncwarp();

        // ---- PV: acc[q][d=4tk+j] += sum_k p[q][k]*v[k][d] ----
        for (int k = 0; k < 64; k++) {
            float4 vf = vs[k*16 + tk];
            #pragma unroll
            for (int i = 0; i < 4; i++) {
                float pv = psf[rq[i]*68 + k];
                acc[i][0] = fmaf(pv, vf.x, acc[i][0]);
                acc[i][1] = fmaf(pv, vf.y, acc[i][1]);
                acc[i][2] = fmaf(pv, vf.z, acc[i][2]);
                acc[i][3] = fmaf(pv, vf.w, acc[i][3]);
            }
        }
    }

    float4* O4 = (float4*)gAtt + (b*Nn + q0) * 16;
    #pragma unroll
    for (int i = 0; i < 4; i++) {
        float inv = 1.f / l_i[i];
        float4 o;
        o.x = acc[i][0]*inv; o.y = acc[i][1]*inv;
        o.z = acc[i][2]*inv; o.w = acc[i][3]*inv;
        O4[rq[i]*16 + tk] = o;
    }
}

// ---------------- K4: output projection o = Wproj @ att ----------------
__global__ void __launch_bounds__(256) projout_kernel(const float* __restrict__ Wproj)
{
    __shared__ float as_[64*65];
    __shared__ float wo[64*65];
    int b  = blockIdx.y;
    int n0 = blockIdx.x << 6;
    int t  = threadIdx.x;

    for (int idx = t; idx < 4096; idx += 256) {
        int nn = idx >> 6, d = idx & 63;
        as_[nn*65 + d] = gAtt[(b*Nn + n0 + nn)*64 + d];
    }
    for (int idx = t; idx < 4096; idx += 256) wo[idx] = Wproj[idx];  // [c][d]
    __syncthreads();

    int n = t & 63, g = t >> 6;
    float acc[16];
    #pragma unroll
    for (int i = 0; i < 16; i++) acc[i] = 0.f;
    for (int d = 0; d < 64; d++) {
        float av = as_[n*65 + d];
        #pragma unroll
        for (int i = 0; i < 16; i++)
            acc[i] = fmaf(wo[(g*16 + i)*64 + d], av, acc[i]);
    }
    __syncthreads();
    #pragma unroll
    for (int i = 0; i < 16; i++) wo[n*65 + g*16 + i] = acc[i];
    __syncthreads();
    for (int idx = t; idx < 4096; idx += 256) {
        int nn = idx >> 6, c = idx & 63;
        gO[(b*Nn + n0 + nn)*64 + c] = wo[nn*65 + c];
    }
}

// ---------------- K5: FFN (W1 -> exact GELU -> W2), writes gY channel-major ----------------
#define FFN_SMEM_FLOATS (64*65 + HIDD*Cc + 64*257 + Cc*HIDD)  // os, w1, hs, w2

__global__ void __launch_bounds__(256) ffn_kernel(
    const float* __restrict__ W1, const float* __restrict__ W2)
{
    extern __shared__ float smf[];
    float* os  = smf;                         // [64 tokens][65]
    float* w1s = os  + 64*65;                 // [256][64]
    float* hs  = w1s + HIDD*Cc;               // [64 tokens][257]
    float* w2s = hs  + 64*257;                // [64][256]

    int b  = blockIdx.y;
    int n0 = blockIdx.x << 6;
    int t  = threadIdx.x;

    for (int idx = t; idx < 4096; idx += 256) {
        int nn = idx >> 6, c = idx & 63;
        os[nn*65 + c] = gO[(b*Nn + n0 + nn)*64 + c];
    }
    for (int idx = t; idx < HIDD*Cc; idx += 256) w1s[idx] = W1[idx];
    for (int idx = t; idx < Cc*HIDD; idx += 256) w2s[idx] = W2[idx];
    __syncthreads();

    int n = t & 63, g = t >> 6;

    // hidden: each thread computes 64 of the 256 e-dims for its token
    for (int ee = 0; ee < 64; ee++) {
        int e = g*64 + ee;
        float a = 0.f;
        const float* wr = w1s + e*64;
        #pragma unroll 8
        for (int c = 0; c < 64; c++) a = fmaf(wr[c], os[n*65 + c], a);
        float gl = 0.5f * a * (1.f + erff(a * 0.70710678118654752f));
        hs[n*257 + e] = gl;
    }
    __syncthreads();

    // y: each thread 16 channels of its token
    float acc[16];
    #pragma unroll
    for (int i = 0; i < 16; i++) acc[i] = 0.f;
    for (int e = 0; e < 256; e++) {
        float hv = hs[n*257 + e];
        #pragma unroll
        for (int i = 0; i < 16; i++)
            acc[i] = fmaf(w2s[(g*16 + i)*256 + e], hv, acc[i]);
    }
    // channel-major store (coalesced over n)
    #pragma unroll
    for (int i = 0; i < 16; i++) {
        int c = g*16 + i;
        gY[((b<<6) + c)*Nn + n0 + n] = acc[i];
    }
}

// ---------------- K6: BN statistics per channel ----------------
__global__ void __launch_bounds__(256) bnstats_kernel()
{
    __shared__ float rs[256], rs2[256];
    int c = blockIdx.x;
    int t = threadIdx.x;
    float s = 0.f, s2 = 0.f;
    for (int idx = t; idx < Bsz*Nn; idx += 256) {
        int b = idx >> 12, n = idx & (Nn - 1);
        float v = gY[((b<<6) + c)*Nn + n];
        s += v; s2 = fmaf(v, v, s2);
    }
    rs[t] = s; rs2[t] = s2;
    __syncthreads();
    for (int d = 128; d > 0; d >>= 1) {
        if (t < d) { rs[t] += rs[t + d]; rs2[t] += rs2[t + d]; }
        __syncthreads();
    }
    if (t == 0) {
        float mean = rs[0] * (1.f / (Bsz*Nn));
        float var  = rs2[0] * (1.f / (Bsz*Nn)) - mean*mean;
        gStats[c]      = mean;
        gStats[64 + c] = rsqrtf(var + EPSBN);
    }
}

// ---------------- K7: apply BN + residual ----------------
__global__ void bnapply_kernel(const float* __restrict__ gamma,
                               const float* __restrict__ beta,
                               float* __restrict__ out)
{
    int i = blockIdx.x * blockDim.x + threadIdx.x;
    int c = (i >> 12) & 63;
    float mean = gStats[c], inv = gStats[64 + c];
    out[i] = (gY[i] - mean) * inv * gamma[c] + beta[c] + gFl[i];
}

// ---------------- launch ----------------
extern "C" void kernel_launch(void* const* d_in, const int* in_sizes, int n_in,
                              void* d_out, int out_size)
{
    const float* Fs    = (const float*)d_in[0];
    const float* Ff    = (const float*)d_in[1];
    const float* Wq1   = (const float*)d_in[2];
    const float* Wk1   = (const float*)d_in[3];
    const float* Wq2   = (const float*)d_in[4];
    const float* Wk2   = (const float*)d_in[5];
    const float* Wv    = (const float*)d_in[6];
    const float* Wproj = (const float*)d_in[7];
    const float* W1    = (const float*)d_in[8];
    const float* W2    = (const float*)d_in[9];
    const float* gamma = (const float*)d_in[10];
    const float* beta  = (const float*)d_in[11];
    const float* lam   = (const float*)d_in[12];
    float* out = (float*)d_out;

    add_kernel<<<(Bsz*Cc*Nn)/256, 256>>>(Fs, Ff);
    proj_kernel<<<dim3(64, Bsz), 256>>>(Wq1, Wk1, Wq2, Wk2, Wv, lam);

    size_t flash_smem = (size_t)FLASH_SMEM_F4 * sizeof(float4);
    cudaFuncSetAttribute(flash_kernel, cudaFuncAttributeMaxDynamicSharedMemorySize, (int)flash_smem);
    flash_kernel<<<dim3(64, Bsz), 256, flash_smem>>>();

    projout_kernel<<<dim3(64, Bsz), 256>>>(Wproj);

    size_t ffn_smem = (size_t)FFN_SMEM_FLOATS * sizeof(float);
    cudaFuncSetAttribute(ffn_kernel, cudaFuncAttributeMaxDynamicSharedMemorySize, (int)ffn_smem);
    ffn_kernel<<<dim3(64, Bsz), 256, ffn_smem>>>(W1, W2);

    bnstats_kernel<<<Cc, 256>>>();
    bnapply_kernel<<<(Bsz*Cc*Nn)/256, 256>>>(gamma, beta, out);
}

// round 2
// speedup vs baseline: 3.5714x; 3.5714x over previous
#include <cuda_runtime.h>
#include <math.h>
#include <stdint.h>

// Problem constants
#define Bsz 4
#define Cc  64
#define Nn  4096
#define Dd  64
#define HIDD 256
#define EPSBN 1e-5f

// ---------------- scratch (__device__ globals; no allocation) ----------------
__device__ float gFl [Bsz*Cc*Nn];     // Fs+Ff, channel-major [B][C][N]
__device__ float gQT [Bsz*Nn*128];    // [scale*q1 | -scale*lam*q2], token-major [B][N][128]
__device__ float gKT [Bsz*Nn*128];    // [k1 | k2]
__device__ float gV  [Bsz*Nn*Dd];     // v, token-major
__device__ float gAtt[Bsz*Nn*Dd];     // attention output, token-major
__device__ float gO  [Bsz*Nn*Cc];     // Wproj @ att, token-major
__device__ float gY  [Bsz*Cc*Nn];     // FFN output, channel-major
__device__ float gStats[2*Cc];        // mean[64], invstd[64]

// ---------------- helpers ----------------
__device__ __forceinline__ float to_tf32(float x) {
    uint32_t u;
    asm("cvt.rna.tf32.f32 %0, %1;" : "=r"(u) : "f"(x));
    return __uint_as_float(u);
}

// D += A(16x8,row) * B(8x8,col)   tf32 inputs (in fp32 containers), fp32 accum
__device__ __forceinline__ void mma_tf32(float* c, const float* a, float b0, float b1) {
    asm volatile(
        "mma.sync.aligned.m16n8k8.row.col.f32.tf32.tf32.f32 "
        "{%0,%1,%2,%3}, {%4,%5,%6,%7}, {%8,%9}, {%0,%1,%2,%3};"
        : "+f"(c[0]), "+f"(c[1]), "+f"(c[2]), "+f"(c[3])
        : "r"(__float_as_uint(a[0])), "r"(__float_as_uint(a[1])),
          "r"(__float_as_uint(a[2])), "r"(__float_as_uint(a[3])),
          "r"(__float_as_uint(b0)),   "r"(__float_as_uint(b1)));
}

// ---------------- K1: Fl = Fs + Ff ----------------
__global__ void add_kernel(const float* __restrict__ a, const float* __restrict__ b) {
    int i = blockIdx.x * blockDim.x + threadIdx.x;
    gFl[i] = a[i] + b[i];
}

// ---------------- K2: 5 input projections (1x1 convs) ----------------
__global__ void __launch_bounds__(256) proj_kernel(
    const float* __restrict__ Wq1, const float* __restrict__ Wk1,
    const float* __restrict__ Wq2, const float* __restrict__ Wk2,
    const float* __restrict__ Wv,  const float* __restrict__ lam_p)
{
    __shared__ float xs[64*65];   // x tile [c][n], padded
    __shared__ float wo[64*65];   // weight buffer, then output-transpose buffer

    int b  = blockIdx.y;
    int n0 = blockIdx.x << 6;
    int t  = threadIdx.x;

    for (int idx = t; idx < 4096; idx += 256) {
        int c = idx >> 6, nn = idx & 63;
        xs[c*65 + nn] = gFl[((b<<6) + c)*Nn + n0 + nn];
    }
    float lam = __ldg(lam_p);
    const float* Ws[5] = {Wq1, Wk1, Wq2, Wk2, Wv};
    const float  scl[5] = {0.125f, 1.0f, -0.125f*lam, 1.0f, 1.0f};

    int n = t & 63, g = t >> 6;

    for (int m = 0; m < 5; m++) {
        __syncthreads();
        for (int idx = t; idx < 4096; idx += 256) wo[idx] = Ws[m][idx];  // W[d][c]
        __syncthreads();

        float acc[16];
        #pragma unroll
        for (int i = 0; i < 16; i++) acc[i] = 0.f;

        for (int c = 0; c < 64; c++) {
            float xv = xs[c*65 + n];
            #pragma unroll
            for (int i = 0; i < 16; i++)
                acc[i] = fmaf(wo[(g*16 + i)*64 + c], xv, acc[i]);
        }
        __syncthreads();
        float s = scl[m];
        #pragma unroll
        for (int i = 0; i < 16; i++) wo[n*65 + g*16 + i] = acc[i] * s;
        __syncthreads();

        float* dst; int stride, off;
        if      (m == 0) { dst = gQT; stride = 128; off = 0;  }
        else if (m == 1) { dst = gKT; stride = 128; off = 0;  }
        else if (m == 2) { dst = gQT; stride = 128; off = 64; }
        else if (m == 3) { dst = gKT; stride = 128; off = 64; }
        else             { dst = gV;  stride = 64;  off = 0;  }

        for (int idx = t; idx < 4096; idx += 256) {
            int nn = idx >> 6, d = idx & 63;
            dst[(b*Nn + n0 + nn)*stride + off + d] = wo[nn*65 + d];
        }
    }
}

// ---------------- K3: flash attention, tf32 tensor-core MMA ----------------
// 128 threads = 4 warps; block handles 64 queries; each warp owns 16 query rows.
// K-tile = 64 keys. QK over 128 dims, PV over 64 dims, online softmax in fp32.
// smem: ks[64][132] (K tile; also Q staging), vs[64][68] (V), psm[64][68] (P).
#define KS_STRIDE 132
#define VS_STRIDE 68
#define PS_STRIDE 68
#define FLASH_SMEM_FLOATS (64*KS_STRIDE + 64*VS_STRIDE + 64*PS_STRIDE)

__global__ void __launch_bounds__(128) flash_tc_kernel()
{
    extern __shared__ float smf[];
    float* ks  = smf;                      // 64 x 132
    float* vs  = ks  + 64*KS_STRIDE;       // 64 x 68
    float* psm = vs  + 64*VS_STRIDE;       // 64 x 68

    int b  = blockIdx.y;
    int q0 = blockIdx.x << 6;
    int t  = threadIdx.x;
    int w    = t >> 5;
    int lane = t & 31;
    int g    = lane >> 2;    // groupID 0..7
    int tig  = lane & 3;     // thread-in-group 0..3

    const float4* QT = (const float4*)gQT + (size_t)(b*Nn + q0) * 32;
    const float4* KT = (const float4*)gKT + (size_t)b*Nn * 32;
    const float4* V4 = (const float4*)gV  + (size_t)b*Nn * 16;

    // ---- stage Q tile (tf32-rounded) into ks, then pull A-fragments into regs ----
    for (int idx = t; idx < 64*32; idx += 128) {
        int r = idx >> 5, c4 = idx & 31;
        float4 v = QT[r*32 + c4];
        float* d = &ks[r*KS_STRIDE + c4*4];
        d[0] = to_tf32(v.x); d[1] = to_tf32(v.y);
        d[2] = to_tf32(v.z); d[3] = to_tf32(v.w);
    }
    __syncthreads();

    int row0 = w*16 + g;
    int row1 = row0 + 8;

    float qa[16][4];
    #pragma unroll
    for (int kst = 0; kst < 16; kst++) {
        qa[kst][0] = ks[row0*KS_STRIDE + kst*8 + tig];
        qa[kst][1] = ks[row1*KS_STRIDE + kst*8 + tig];
        qa[kst][2] = ks[row0*KS_STRIDE + kst*8 + tig + 4];
        qa[kst][3] = ks[row1*KS_STRIDE + kst*8 + tig + 4];
    }

    float oc[8][4];
    #pragma unroll
    for (int nt = 0; nt < 8; nt++)
        #pragma unroll
        for (int j = 0; j < 4; j++) oc[nt][j] = 0.f;
    float m0 = -1e30f, m1 = -1e30f, l0 = 0.f, l1 = 0.f;

    for (int kt0 = 0; kt0 < Nn; kt0 += 64) {
        __syncthreads();  // previous tile's ks/vs/psm reads are done

        // load K tile (64 x 128) and V tile (64 x 64), tf32-rounded
        for (int idx = t; idx < 64*32; idx += 128) {
            int r = idx >> 5, c4 = idx & 31;
            float4 v = KT[(kt0 + r)*32 + c4];
            float* d = &ks[r*KS_STRIDE + c4*4];
            d[0] = to_tf32(v.x); d[1] = to_tf32(v.y);
            d[2] = to_tf32(v.z); d[3] = to_tf32(v.w);
        }
        for (int idx = t; idx < 64*16; idx += 128) {
            int r = idx >> 4, c4 = idx & 15;
            float4 v = V4[(kt0 + r)*16 + c4];
            float* d = &vs[r*VS_STRIDE + c4*4];
            d[0] = to_tf32(v.x); d[1] = to_tf32(v.y);
            d[2] = to_tf32(v.z); d[3] = to_tf32(v.w);
        }
        __syncthreads();

        // ---- S = Q . K^T  (16 rows x 64 keys per warp) ----
        float sc[8][4];
        #pragma unroll
        for (int nt = 0; nt < 8; nt++) {
            sc[nt][0] = sc[nt][1] = sc[nt][2] = sc[nt][3] = 0.f;
            const float* kb = &ks[(nt*8 + g)*KS_STRIDE];
            #pragma unroll
            for (int kst = 0; kst < 16; kst++) {
                float b0 = kb[kst*8 + tig];
                float b1 = kb[kst*8 + tig + 4];
                mma_tf32(sc[nt], qa[kst], b0, b1);
            }
        }

        // ---- online softmax ----
        float mx0 = -1e30f, mx1 = -1e30f;
        #pragma unroll
        for (int nt = 0; nt < 8; nt++) {
            mx0 = fmaxf(mx0, fmaxf(sc[nt][0], sc[nt][1]));
            mx1 = fmaxf(mx1, fmaxf(sc[nt][2], sc[nt][3]));
        }
        mx0 = fmaxf(mx0, __shfl_xor_sync(0xffffffffu, mx0, 1));
        mx0 = fmaxf(mx0, __shfl_xor_sync(0xffffffffu, mx0, 2));
        mx1 = fmaxf(mx1, __shfl_xor_sync(0xffffffffu, mx1, 1));
        mx1 = fmaxf(mx1, __shfl_xor_sync(0xffffffffu, mx1, 2));

        float mn0 = fmaxf(m0, mx0), mn1 = fmaxf(m1, mx1);
        float cr0 = __expf(m0 - mn0), cr1 = __expf(m1 - mn1);
        m0 = mn0; m1 = mn1;

        float sum0 = 0.f, sum1 = 0.f;
        #pragma unroll
        for (int nt = 0; nt < 8; nt++) {
            float p00 = __expf(sc[nt][0] - mn0);
            float p01 = __expf(sc[nt][1] - mn0);
            float p10 = __expf(sc[nt][2] - mn1);
            float p11 = __expf(sc[nt][3] - mn1);
            sum0 += p00 + p01;
            sum1 += p10 + p11;
            int cc = nt*8 + 2*tig;
            psm[row0*PS_STRIDE + cc]     = to_tf32(p00);
            psm[row0*PS_STRIDE + cc + 1] = to_tf32(p01);
            psm[row1*PS_STRIDE + cc]     = to_tf32(p10);
            psm[row1*PS_STRIDE + cc + 1] = to_tf32(p11);
            oc[nt][0] *= cr0; oc[nt][1] *= cr0;
            oc[nt][2] *= cr1; oc[nt][3] *= cr1;
        }
        sum0 += __shfl_xor_sync(0xffffffffu, sum0, 1);
        sum0 += __shfl_xor_sync(0xffffffffu, sum0, 2);
        sum1 += __shfl_xor_sync(0xffffffffu, sum1, 1);
        sum1 += __shfl_xor_sync(0xffffffffu, sum1, 2);
        l0 = l0*cr0 + sum0;
        l1 = l1*cr1 + sum1;

        __syncwarp();  // P rows of this warp visible to all its lanes

        // ---- O += P . V  (K-dim = 64 keys) ----
        #pragma unroll
        for (int kst = 0; kst < 8; kst++) {
            float pa[4];
            pa[0] = psm[row0*PS_STRIDE + kst*8 + tig];
            pa[1] = psm[row1*PS_STRIDE + kst*8 + tig];
            pa[2] = psm[row0*PS_STRIDE + kst*8 + tig + 4];
            pa[3] = psm[row1*PS_STRIDE + kst*8 + tig + 4];
            #pragma unroll
            for (int nt = 0; nt < 8; nt++) {
                float b0 = vs[(kst*8 + tig)*VS_STRIDE + nt*8 + g];
                float b1 = vs[(kst*8 + tig + 4)*VS_STRIDE + nt*8 + g];
                mma_tf32(oc[nt], pa, b0, b1);
            }
        }
    }

    // ---- normalize and store ----
    float inv0 = 1.f / l0, inv1 = 1.f / l1;
    float* O = gAtt + (size_t)(b*Nn + q0) * 64;
    #pragma unroll
    for (int nt = 0; nt < 8; nt++) {
        int cc = nt*8 + 2*tig;
        float2 o0 = make_float2(oc[nt][0]*inv0, oc[nt][1]*inv0);
        float2 o1 = make_float2(oc[nt][2]*inv1, oc[nt][3]*inv1);
        *(float2*)&O[(size_t)row0*64 + cc] = o0;
        *(float2*)&O[(size_t)row1*64 + cc] = o1;
    }
}

// ---------------- K4: output projection o = Wproj @ att ----------------
__global__ void __launch_bounds__(256) projout_kernel(const float* __restrict__ Wproj)
{
    __shared__ float as_[64*65];
    __shared__ float wo[64*65];
    int b  = blockIdx.y;
    int n0 = blockIdx.x << 6;
    int t  = threadIdx.x;

    for (int idx = t; idx < 4096; idx += 256) {
        int nn = idx >> 6, d = idx & 63;
        as_[nn*65 + d] = gAtt[(b*Nn + n0 + nn)*64 + d];
    }
    for (int idx = t; idx < 4096; idx += 256) wo[idx] = Wproj[idx];  // [c][d]
    __syncthreads();

    int n = t & 63, g = t >> 6;
    float acc[16];
    #pragma unroll
    for (int i = 0; i < 16; i++) acc[i] = 0.f;
    for (int d = 0; d < 64; d++) {
        float av = as_[n*65 + d];
        #pragma unroll
        for (int i = 0; i < 16; i++)
            acc[i] = fmaf(wo[(g*16 + i)*64 + d], av, acc[i]);
    }
    __syncthreads();
    #pragma unroll
    for (int i = 0; i < 16; i++) wo[n*65 + g*16 + i] = acc[i];
    __syncthreads();
    for (int idx = t; idx < 4096; idx += 256) {
        int nn = idx >> 6, c = idx & 63;
        gO[(b*Nn + n0 + nn)*64 + c] = wo[nn*65 + c];
    }
}

// ---------------- K5: FFN (W1 -> exact GELU -> W2), writes gY channel-major ----------------
#define FFN_SMEM_FLOATS (64*65 + HIDD*Cc + 64*257 + Cc*HIDD)  // os, w1, hs, w2

__global__ void __launch_bounds__(256) ffn_kernel(
    const float* __restrict__ W1, const float* __restrict__ W2)
{
    extern __shared__ float smf[];
    float* os  = smf;                         // [64 tokens][65]
    float* w1s = os  + 64*65;                 // [256][64]
    float* hs  = w1s + HIDD*Cc;               // [64 tokens][257]
    float* w2s = hs  + 64*257;                // [64][256]

    int b  = blockIdx.y;
    int n0 = blockIdx.x << 6;
    int t  = threadIdx.x;

    for (int idx = t; idx < 4096; idx += 256) {
        int nn = idx >> 6, c = idx & 63;
        os[nn*65 + c] = gO[(b*Nn + n0 + nn)*64 + c];
    }
    for (int idx = t; idx < HIDD*Cc; idx += 256) w1s[idx] = W1[idx];
    for (int idx = t; idx < Cc*HIDD; idx += 256) w2s[idx] = W2[idx];
    __syncthreads();

    int n = t & 63, g = t >> 6;

    for (int ee = 0; ee < 64; ee++) {
        int e = g*64 + ee;
        float a = 0.f;
        const float* wr = w1s + e*64;
        #pragma unroll 8
        for (int c = 0; c < 64; c++) a = fmaf(wr[c], os[n*65 + c], a);
        float gl = 0.5f * a * (1.f + erff(a * 0.70710678118654752f));
        hs[n*257 + e] = gl;
    }
    __syncthreads();

    float acc[16];
    #pragma unroll
    for (int i = 0; i < 16; i++) acc[i] = 0.f;
    for (int e = 0; e < 256; e++) {
        float hv = hs[n*257 + e];
        #pragma unroll
        for (int i = 0; i < 16; i++)
            acc[i] = fmaf(w2s[(g*16 + i)*256 + e], hv, acc[i]);
    }
    #pragma unroll
    for (int i = 0; i < 16; i++) {
        int c = g*16 + i;
        gY[((b<<6) + c)*Nn + n0 + n] = acc[i];
    }
}

// ---------------- K6: BN statistics per channel ----------------
__global__ void __launch_bounds__(256) bnstats_kernel()
{
    __shared__ float rs[256], rs2[256];
    int c = blockIdx.x;
    int t = threadIdx.x;
    float s = 0.f, s2 = 0.f;
    for (int idx = t; idx < Bsz*Nn; idx += 256) {
        int b = idx >> 12, n = idx & (Nn - 1);
        float v = gY[((b<<6) + c)*Nn + n];
        s += v; s2 = fmaf(v, v, s2);
    }
    rs[t] = s; rs2[t] = s2;
    __syncthreads();
    for (int d = 128; d > 0; d >>= 1) {
        if (t < d) { rs[t] += rs[t + d]; rs2[t] += rs2[t + d]; }
        __syncthreads();
    }
    if (t == 0) {
        float mean = rs[0] * (1.f / (Bsz*Nn));
        float var  = rs2[0] * (1.f / (Bsz*Nn)) - mean*mean;
        gStats[c]      = mean;
        gStats[64 + c] = rsqrtf(var + EPSBN);
    }
}

// ---------------- K7: apply BN + residual ----------------
__global__ void bnapply_kernel(const float* __restrict__ gamma,
                               const float* __restrict__ beta,
                               float* __restrict__ out)
{
    int i = blockIdx.x * blockDim.x + threadIdx.x;
    int c = (i >> 12) & 63;
    float mean = gStats[c], inv = gStats[64 + c];
    out[i] = (gY[i] - mean) * inv * gamma[c] + beta[c] + gFl[i];
}

// ---------------- launch ----------------
extern "C" void kernel_launch(void* const* d_in, const int* in_sizes, int n_in,
                              void* d_out, int out_size)
{
    const float* Fs    = (const float*)d_in[0];
    const float* Ff    = (const float*)d_in[1];
    const float* Wq1   = (const float*)d_in[2];
    const float* Wk1   = (const float*)d_in[3];
    const float* Wq2   = (const float*)d_in[4];
    const float* Wk2   = (const float*)d_in[5];
    const float* Wv    = (const float*)d_in[6];
    const float* Wproj = (const float*)d_in[7];
    const float* W1    = (const float*)d_in[8];
    const float* W2    = (const float*)d_in[9];
    const float* gamma = (const float*)d_in[10];
    const float* beta  = (const float*)d_in[11];
    const float* lam   = (const float*)d_in[12];
    float* out = (float*)d_out;

    add_kernel<<<(Bsz*Cc*Nn)/256, 256>>>(Fs, Ff);
    proj_kernel<<<dim3(64, Bsz), 256>>>(Wq1, Wk1, Wq2, Wk2, Wv, lam);

    size_t flash_smem = (size_t)FLASH_SMEM_FLOATS * sizeof(float);
    cudaFuncSetAttribute(flash_tc_kernel, cudaFuncAttributeMaxDynamicSharedMemorySize, (int)flash_smem);
    flash_tc_kernel<<<dim3(64, Bsz), 128, flash_smem>>>();

    projout_kernel<<<dim3(64, Bsz), 256>>>(Wproj);

    size_t ffn_smem = (size_t)FFN_SMEM_FLOATS * sizeof(float);
    cudaFuncSetAttribute(ffn_kernel, cudaFuncAttributeMaxDynamicSharedMemorySize, (int)ffn_smem);
    ffn_kernel<<<dim3(64, Bsz), 256, ffn_smem>>>(W1, W2);

    bnstats_kernel<<<Cc, 256>>>();
    bnapply_kernel<<<(Bsz*Cc*Nn)/256, 256>>>(gamma, beta, out);
}

// round 3
// speedup vs baseline: 6.4529x; 1.8068x over previous
#include <cuda_runtime.h>
#include <cuda_fp16.h>
#include <math.h>
#include <stdint.h>

// Problem constants
#define Bsz 4
#define Cc  64
#define Nn  4096
#define HIDD 256
#define EPSBN 1e-5f

// ---------------- scratch (__device__ globals; no allocation) ----------------
__device__ float  gFl [Bsz*Cc*Nn];     // Fs+Ff, channel-major [B][C][N] (fp32, exact residual)
__device__ __half gQ  [Bsz*Nn*128];    // [0.125*q1 | -0.125*lam*q2], token-major [B][N][128]
__device__ __half gK  [Bsz*Nn*128];    // [k1 | k2], token-major
__device__ __half gVT [Bsz*Cc*Nn];     // v, d-major [B][D][N]
__device__ __half gO  [Bsz*Nn*Cc];     // Wproj @ attention-out, token-major
__device__ float  gY  [Bsz*Cc*Nn];     // FFN output, channel-major (fp32 for BN stats)
__device__ float  gStats[2*Cc];        // mean[64], invstd[64]

// ---------------- mma m16n8k16 fp16 in / fp32 accum ----------------
__device__ __forceinline__ void mma_f16(float* c, const uint32_t* a, uint32_t b0, uint32_t b1) {
    asm volatile(
        "mma.sync.aligned.m16n8k16.row.col.f32.f16.f16.f32 "
        "{%0,%1,%2,%3}, {%4,%5,%6,%7}, {%8,%9}, {%0,%1,%2,%3};"
        : "+f"(c[0]), "+f"(c[1]), "+f"(c[2]), "+f"(c[3])
        : "r"(a[0]), "r"(a[1]), "r"(a[2]), "r"(a[3]), "r"(b0), "r"(b1));
}

__device__ __forceinline__ uint32_t pack2(float x, float y) {
    __half2 h = __floats2half2_rn(x, y);
    return *(uint32_t*)&h;
}

// ---------------- K1: Fl = Fs + Ff ----------------
__global__ void add_kernel(const float* __restrict__ a, const float* __restrict__ b) {
    int i = blockIdx.x * blockDim.x + threadIdx.x;
    gFl[i] = a[i] + b[i];
}

// ---------------- K2: 5 input projections, fp16 MMA ----------------
// Block = 64 tokens of one batch, 4 warps, warp owns 16 token rows.
#define XS_LD 72
#define PROJ_SMEM_HALFS (64*XS_LD + 5*64*XS_LD)

__global__ void __launch_bounds__(128) proj_kernel(
    const float* __restrict__ Wq1, const float* __restrict__ Wk1,
    const float* __restrict__ Wq2, const float* __restrict__ Wk2,
    const float* __restrict__ Wv,  const float* __restrict__ lam_p)
{
    extern __shared__ __half sh[];
    __half* xs = sh;                 // [64 tok][72]  (x transposed to token-major)
    __half* ws = sh + 64*XS_LD;      // [5][64 d][72]

    int b  = blockIdx.y;
    int n0 = blockIdx.x << 6;
    int t  = threadIdx.x;
    int w = t >> 5, lane = t & 31, g = lane >> 2, t4 = lane & 3;

    // stage x: gFl channel-major -> xs[token][c] fp16
    for (int idx = t; idx < 4096; idx += 128) {
        int c = idx >> 6, n = idx & 63;
        xs[n*XS_LD + c] = __float2half(gFl[((b<<6) + c)*Nn + n0 + n]);
    }
    const float* Wsrc[5] = {Wq1, Wk1, Wq2, Wk2, Wv};
    for (int m = 0; m < 5; m++)
        for (int idx = t; idx < 4096; idx += 128) {
            int d = idx >> 6, c = idx & 63;
            ws[(m*64 + d)*XS_LD + c] = __float2half(Wsrc[m][idx]);
        }
    __syncthreads();

    float lam = __ldg(lam_p);
    float scl[5] = {0.125f, 1.0f, -0.125f*lam, 1.0f, 1.0f};

    int row0 = w*16 + g;

    // A-fragments of x (k = channel, 4 k-steps of 16)
    uint32_t xa[4][4];
    #pragma unroll
    for (int ks = 0; ks < 4; ks++) {
        xa[ks][0] = *(uint32_t*)&xs[ row0     *XS_LD + 16*ks + 2*t4];
        xa[ks][1] = *(uint32_t*)&xs[(row0 + 8)*XS_LD + 16*ks + 2*t4];
        xa[ks][2] = *(uint32_t*)&xs[ row0     *XS_LD + 16*ks + 2*t4 + 8];
        xa[ks][3] = *(uint32_t*)&xs[(row0 + 8)*XS_LD + 16*ks + 2*t4 + 8];
    }

    for (int m = 0; m < 5; m++) {
        float acc[8][4];
        #pragma unroll
        for (int nt = 0; nt < 8; nt++)
            acc[nt][0] = acc[nt][1] = acc[nt][2] = acc[nt][3] = 0.f;

        const __half* wm = ws + m*64*XS_LD;
        #pragma unroll
        for (int nt = 0; nt < 8; nt++) {
            const __half* wrow = wm + (nt*8 + g)*XS_LD;
            #pragma unroll
            for (int ks = 0; ks < 4; ks++) {
                uint32_t b0 = *(uint32_t*)&wrow[16*ks + 2*t4];
                uint32_t b1 = *(uint32_t*)&wrow[16*ks + 2*t4 + 8];
                mma_f16(acc[nt], xa[ks], b0, b1);
            }
        }
        float s = scl[m];

        if (m == 4) {
            // V: write d-major gVT[(b*64+d)*Nn + n]
            #pragma unroll
            for (int nt = 0; nt < 8; nt++) {
                int d0 = nt*8 + 2*t4;
                gVT[((b<<6) + d0    )*Nn + n0 + row0    ] = __float2half(acc[nt][0]*s);
                gVT[((b<<6) + d0 + 1)*Nn + n0 + row0    ] = __float2half(acc[nt][1]*s);
                gVT[((b<<6) + d0    )*Nn + n0 + row0 + 8] = __float2half(acc[nt][2]*s);
                gVT[((b<<6) + d0 + 1)*Nn + n0 + row0 + 8] = __float2half(acc[nt][3]*s);
            }
        } else {
            __half* dst = (m == 0 || m == 2) ? gQ : gK;
            int off = (m >= 2) ? 64 : 0;
            #pragma unroll
            for (int nt = 0; nt < 8; nt++) {
                uint32_t p0 = pack2(acc[nt][0]*s, acc[nt][1]*s);
                uint32_t p1 = pack2(acc[nt][2]*s, acc[nt][3]*s);
                *(uint32_t*)&dst[(size_t)(b*Nn + n0 + row0    )*128 + off + nt*8 + 2*t4] = p0;
                *(uint32_t*)&dst[(size_t)(b*Nn + n0 + row0 + 8)*128 + off + nt*8 + 2*t4] = p1;
            }
        }
    }
}

// ---------------- K3: flash attention fp16 MMA + fused output projection ----------------
// Block = 64 queries, 4 warps x 16 rows. K-tile = 64 keys. P stays in registers.
#define KS_LD 136
#define VT_LD 72
#define WP_LD 72
#define FLASH_SMEM_HALFS (64*KS_LD + 64*VT_LD + 64*WP_LD)

__global__ void __launch_bounds__(128) flash_kernel(const float* __restrict__ Wproj)
{
    extern __shared__ __half sh[];
    __half* ks  = sh;                       // Q staging, then K tiles [64][136]
    __half* vsT = sh + 64*KS_LD;            // V^T tile [d=64][key 64 +pad]
    __half* wp  = vsT + 64*VT_LD;           // Wproj [c=64][d 64 +pad]

    int b  = blockIdx.y;
    int q0 = blockIdx.x << 6;
    int t  = threadIdx.x;
    int w = t >> 5, lane = t & 31, g = lane >> 2, t4 = lane & 3;
    int row0 = w*16 + g, row1 = row0 + 8;

    // stage Wproj fp16
    for (int idx = t; idx < 4096; idx += 128) {
        int c = idx >> 6, d = idx & 63;
        wp[c*WP_LD + d] = __float2half(Wproj[idx]);
    }

    // stage Q tile: pure fp16 copy (uint4 = 8 halves)
    const uint4* Qg = (const uint4*)(gQ + (size_t)(b*Nn + q0)*128);
    for (int idx = t; idx < 1024; idx += 128) {
        int r = idx >> 4, ch = idx & 15;
        *(uint4*)&ks[r*KS_LD + ch*8] = Qg[r*16 + ch];
    }
    __syncthreads();

    // Q A-fragments: 8 k-steps of 16 dims
    uint32_t qa[8][4];
    #pragma unroll
    for (int kst = 0; kst < 8; kst++) {
        qa[kst][0] = *(uint32_t*)&ks[row0*KS_LD + 16*kst + 2*t4];
        qa[kst][1] = *(uint32_t*)&ks[row1*KS_LD + 16*kst + 2*t4];
        qa[kst][2] = *(uint32_t*)&ks[row0*KS_LD + 16*kst + 2*t4 + 8];
        qa[kst][3] = *(uint32_t*)&ks[row1*KS_LD + 16*kst + 2*t4 + 8];
    }

    float oc[8][4];
    #pragma unroll
    for (int nt = 0; nt < 8; nt++)
        oc[nt][0] = oc[nt][1] = oc[nt][2] = oc[nt][3] = 0.f;
    float m0 = -1e30f, m1 = -1e30f, l0 = 0.f, l1 = 0.f;

    const uint4*  Kg = (const uint4*)(gK + (size_t)b*Nn*128);
    const uint4*  Vg = (const uint4*)(gVT + (size_t)b*64*Nn);   // rows d, 4096 halves each

    for (int kt0 = 0; kt0 < Nn; kt0 += 64) {
        __syncthreads();
        // K tile copy
        for (int idx = t; idx < 1024; idx += 128) {
            int r = idx >> 4, ch = idx & 15;
            *(uint4*)&ks[r*KS_LD + ch*8] = Kg[(kt0 + r)*16 + ch];
        }
        // V^T tile copy: vsT[d][0..63] = gVT[b][d][kt0..kt0+63]
        for (int idx = t; idx < 512; idx += 128) {
            int d = idx >> 3, ch = idx & 7;
            *(uint4*)&vsT[d*VT_LD + ch*8] = Vg[d*512 + (kt0>>3) + ch];
        }
        __syncthreads();

        // ---- S = Q K^T : 8 n-tiles x 8 k-steps ----
        float sc[8][4];
        #pragma unroll
        for (int nt = 0; nt < 8; nt++) {
            sc[nt][0] = sc[nt][1] = sc[nt][2] = sc[nt][3] = 0.f;
            const __half* kb = &ks[(nt*8 + g)*KS_LD];
            #pragma unroll
            for (int kst = 0; kst < 8; kst++) {
                uint32_t b0 = *(uint32_t*)&kb[16*kst + 2*t4];
                uint32_t b1 = *(uint32_t*)&kb[16*kst + 2*t4 + 8];
                mma_f16(sc[nt], qa[kst], b0, b1);
            }
        }

        // ---- online softmax (fp32) ----
        float mx0 = -1e30f, mx1 = -1e30f;
        #pragma unroll
        for (int nt = 0; nt < 8; nt++) {
            mx0 = fmaxf(mx0, fmaxf(sc[nt][0], sc[nt][1]));
            mx1 = fmaxf(mx1, fmaxf(sc[nt][2], sc[nt][3]));
        }
        mx0 = fmaxf(mx0, __shfl_xor_sync(0xffffffffu, mx0, 1));
        mx0 = fmaxf(mx0, __shfl_xor_sync(0xffffffffu, mx0, 2));
        mx1 = fmaxf(mx1, __shfl_xor_sync(0xffffffffu, mx1, 1));
        mx1 = fmaxf(mx1, __shfl_xor_sync(0xffffffffu, mx1, 2));

        float mn0 = fmaxf(m0, mx0), mn1 = fmaxf(m1, mx1);
        float cr0 = __expf(m0 - mn0), cr1 = __expf(m1 - mn1);
        m0 = mn0; m1 = mn1;

        float sum0 = 0.f, sum1 = 0.f;
        #pragma unroll
        for (int nt = 0; nt < 8; nt++) {
            sc[nt][0] = __expf(sc[nt][0] - mn0);
            sc[nt][1] = __expf(sc[nt][1] - mn0);
            sc[nt][2] = __expf(sc[nt][2] - mn1);
            sc[nt][3] = __expf(sc[nt][3] - mn1);
            sum0 += sc[nt][0] + sc[nt][1];
            sum1 += sc[nt][2] + sc[nt][3];
            oc[nt][0] *= cr0; oc[nt][1] *= cr0;
            oc[nt][2] *= cr1; oc[nt][3] *= cr1;
        }
        sum0 += __shfl_xor_sync(0xffffffffu, sum0, 1);
        sum0 += __shfl_xor_sync(0xffffffffu, sum0, 2);
        sum1 += __shfl_xor_sync(0xffffffffu, sum1, 1);
        sum1 += __shfl_xor_sync(0xffffffffu, sum1, 2);
        l0 = l0*cr0 + sum0;
        l1 = l1*cr1 + sum1;

        // ---- pack P into A-fragments (no smem round-trip) ----
        uint32_t pa[4][4];
        #pragma unroll
        for (int kst = 0; kst < 4; kst++) {
            pa[kst][0] = pack2(sc[2*kst  ][0], sc[2*kst  ][1]);
            pa[kst][1] = pack2(sc[2*kst  ][2], sc[2*kst  ][3]);
            pa[kst][2] = pack2(sc[2*kst+1][0], sc[2*kst+1][1]);
            pa[kst][3] = pack2(sc[2*kst+1][2], sc[2*kst+1][3]);
        }

        // ---- O += P V : 8 n-tiles (d) x 4 k-steps (keys) ----
        #pragma unroll
        for (int nt = 0; nt < 8; nt++) {
            const __half* vb = &vsT[(nt*8 + g)*VT_LD];
            #pragma unroll
            for (int kst = 0; kst < 4; kst++) {
                uint32_t b0 = *(uint32_t*)&vb[16*kst + 2*t4];
                uint32_t b1 = *(uint32_t*)&vb[16*kst + 2*t4 + 8];
                mma_f16(oc[nt], pa[kst], b0, b1);
            }
        }
    }

    // ---- normalize, fuse output projection: gO = (O/l) @ Wproj^T ----
    float inv0 = 1.f / l0, inv1 = 1.f / l1;
    uint32_t oa[4][4];
    #pragma unroll
    for (int kst = 0; kst < 4; kst++) {
        oa[kst][0] = pack2(oc[2*kst  ][0]*inv0, oc[2*kst  ][1]*inv0);
        oa[kst][1] = pack2(oc[2*kst  ][2]*inv1, oc[2*kst  ][3]*inv1);
        oa[kst][2] = pack2(oc[2*kst+1][0]*inv0, oc[2*kst+1][1]*inv0);
        oa[kst][3] = pack2(oc[2*kst+1][2]*inv1, oc[2*kst+1][3]*inv1);
    }
    float po[8][4];
    #pragma unroll
    for (int nt = 0; nt < 8; nt++) {
        po[nt][0] = po[nt][1] = po[nt][2] = po[nt][3] = 0.f;
        const __half* wrow = &wp[(nt*8 + g)*WP_LD];
        #pragma unroll
        for (int kst = 0; kst < 4; kst++) {
            uint32_t b0 = *(uint32_t*)&wrow[16*kst + 2*t4];
            uint32_t b1 = *(uint32_t*)&wrow[16*kst + 2*t4 + 8];
            mma_f16(po[nt], oa[kst], b0, b1);
        }
    }
    #pragma unroll
    for (int nt = 0; nt < 8; nt++) {
        *(uint32_t*)&gO[(size_t)(b*Nn + q0 + row0)*64 + nt*8 + 2*t4] = pack2(po[nt][0], po[nt][1]);
        *(uint32_t*)&gO[(size_t)(b*Nn + q0 + row1)*64 + nt*8 + 2*t4] = pack2(po[nt][2], po[nt][3]);
    }
}

// ---------------- K4: FFN fp16 MMA (W1 -> exact GELU -> W2) ----------------
#define OS_LD 72
#define W1_LD 72
#define W2_LD 264
#define YS_LD 68
#define FFN_SMEM_HALFS (64*OS_LD + HIDD*W1_LD + 64*W2_LD)

__global__ void __launch_bounds__(128) ffn_kernel(
    const float* __restrict__ W1, const float* __restrict__ W2)
{
    extern __shared__ __half sh[];
    __half* os  = sh;                       // [64 tok][72]
    __half* w1s = sh + 64*OS_LD;            // [256 e][72]
    __half* w2s = w1s + HIDD*W1_LD;         // [64 c][264]

    int b  = blockIdx.y;
    int n0 = blockIdx.x << 6;
    int t  = threadIdx.x;
    int w = t >> 5, lane = t & 31, g = lane >> 2, t4 = lane & 3;
    int row0 = w*16 + g;

    // stage o (fp16 copy), W1, W2 (fp32->fp16)
    const uint4* Og = (const uint4*)(gO + (size_t)(b*Nn + n0)*64);
    for (int idx = t; idx < 512; idx += 128) {
        int r = idx >> 3, ch = idx & 7;
        *(uint4*)&os[r*OS_LD + ch*8] = Og[r*8 + ch];
    }
    for (int idx = t; idx < HIDD*64; idx += 128) {
        int e = idx >> 6, c = idx & 63;
        w1s[e*W1_LD + c] = __float2half(W1[idx]);
    }
    for (int idx = t; idx < 64*HIDD; idx += 128) {
        int c = idx >> 8, e = idx & 255;
        w2s[c*W2_LD + e] = __float2half(W2[idx]);
    }
    __syncthreads();

    uint32_t oa[4][4];
    #pragma unroll
    for (int ks = 0; ks < 4; ks++) {
        oa[ks][0] = *(uint32_t*)&os[ row0     *OS_LD + 16*ks + 2*t4];
        oa[ks][1] = *(uint32_t*)&os[(row0 + 8)*OS_LD + 16*ks + 2*t4];
        oa[ks][2] = *(uint32_t*)&os[ row0     *OS_LD + 16*ks + 2*t4 + 8];
        oa[ks][3] = *(uint32_t*)&os[(row0 + 8)*OS_LD + 16*ks + 2*t4 + 8];
    }

    float yacc[8][4];
    #pragma unroll
    for (int nt = 0; nt < 8; nt++)
        yacc[nt][0] = yacc[nt][1] = yacc[nt][2] = yacc[nt][3] = 0.f;

    for (int ch = 0; ch < 4; ch++) {          // 4 hidden chunks of 64
        float hacc[8][4];
        #pragma unroll
        for (int nt = 0; nt < 8; nt++) {
            hacc[nt][0] = hacc[nt][1] = hacc[nt][2] = hacc[nt][3] = 0.f;
            const __half* wrow = &w1s[(ch*64 + nt*8 + g)*W1_LD];
            #pragma unroll
            for (int ks = 0; ks < 4; ks++) {
                uint32_t b0 = *(uint32_t*)&wrow[16*ks + 2*t4];
                uint32_t b1 = *(uint32_t*)&wrow[16*ks + 2*t4 + 8];
                mma_f16(hacc[nt], oa[ks], b0, b1);
            }
        }
        // exact GELU
        #pragma unroll
        for (int nt = 0; nt < 8; nt++)
            #pragma unroll
            for (int j = 0; j < 4; j++) {
                float v = hacc[nt][j];
                hacc[nt][j] = 0.5f * v * (1.f + erff(v * 0.70710678118654752f));
            }
        // pack hidden A-frags
        uint32_t ha[4][4];
        #pragma unroll
        for (int kst = 0; kst < 4; kst++) {
            ha[kst][0] = pack2(hacc[2*kst  ][0], hacc[2*kst  ][1]);
            ha[kst][1] = pack2(hacc[2*kst  ][2], hacc[2*kst  ][3]);
            ha[kst][2] = pack2(hacc[2*kst+1][0], hacc[2*kst+1][1]);
            ha[kst][3] = pack2(hacc[2*kst+1][2], hacc[2*kst+1][3]);
        }
        // y += h_chunk @ W2_chunk^T
        #pragma unroll
        for (int nt = 0; nt < 8; nt++) {
            const __half* wrow = &w2s[(nt*8 + g)*W2_LD + ch*64];
            #pragma unroll
            for (int kst = 0; kst < 4; kst++) {
                uint32_t b0 = *(uint32_t*)&wrow[16*kst + 2*t4];
                uint32_t b1 = *(uint32_t*)&wrow[16*kst + 2*t4 + 8];
                mma_f16(yacc[nt], ha[kst], b0, b1);
            }
        }
    }
    __syncthreads();   // all smem reads done; reuse as fp32 transpose buffer

    float* ys = (float*)sh;   // [64 c][68]
    #pragma unroll
    for (int nt = 0; nt < 8; nt++) {
        int c0 = nt*8 + 2*t4;
        ys[ c0     *YS_LD + row0    ] = yacc[nt][0];
        ys[(c0 + 1)*YS_LD + row0    ] = yacc[nt][1];
        ys[ c0     *YS_LD + row0 + 8] = yacc[nt][2];
        ys[(c0 + 1)*YS_LD + row0 + 8] = yacc[nt][3];
    }
    __syncthreads();
    for (int idx = t; idx < 4096; idx += 128) {
        int c = idx >> 6, n = idx & 63;
        gY[((b<<6) + c)*Nn + n0 + n] = ys[c*YS_LD + n];
    }
}

// ---------------- K5: BN statistics per channel ----------------
__global__ void __launch_bounds__(256) bnstats_kernel()
{
    __shared__ float rs[256], rs2[256];
    int c = blockIdx.x;
    int t = threadIdx.x;
    float s = 0.f, s2 = 0.f;
    for (int idx = t; idx < Bsz*Nn; idx += 256) {
        int b = idx >> 12, n = idx & (Nn - 1);
        float v = gY[((b<<6) + c)*Nn + n];
        s += v; s2 = fmaf(v, v, s2);
    }
    rs[t] = s; rs2[t] = s2;
    __syncthreads();
    for (int d = 128; d > 0; d >>= 1) {
        if (t < d) { rs[t] += rs[t + d]; rs2[t] += rs2[t + d]; }
        __syncthreads();
    }
    if (t == 0) {
        float mean = rs[0] * (1.f / (Bsz*Nn));
        float var  = rs2[0] * (1.f / (Bsz*Nn)) - mean*mean;
        gStats[c]      = mean;
        gStats[64 + c] = rsqrtf(var + EPSBN);
    }
}

// ---------------- K6: apply BN + residual ----------------
__global__ void bnapply_kernel(const float* __restrict__ gamma,
                               const float* __restrict__ beta,
                               float* __restrict__ out)
{
    int i = blockIdx.x * blockDim.x + threadIdx.x;
    int c = (i >> 12) & 63;
    float mean = gStats[c], inv = gStats[64 + c];
    out[i] = (gY[i] - mean) * inv * gamma[c] + beta[c] + gFl[i];
}

// ---------------- launch ----------------
extern "C" void kernel_launch(void* const* d_in, const int* in_sizes, int n_in,
                              void* d_out, int out_size)
{
    const float* Fs    = (const float*)d_in[0];
    const float* Ff    = (const float*)d_in[1];
    const float* Wq1   = (const float*)d_in[2];
    const float* Wk1   = (const float*)d_in[3];
    const float* Wq2   = (const float*)d_in[4];
    const float* Wk2   = (const float*)d_in[5];
    const float* Wv    = (const float*)d_in[6];
    const float* Wproj = (const float*)d_in[7];
    const float* W1    = (const float*)d_in[8];
    const float* W2    = (const float*)d_in[9];
    const float* gamma = (const float*)d_in[10];
    const float* beta  = (const float*)d_in[11];
    const float* lam   = (const float*)d_in[12];
    float* out = (float*)d_out;

    add_kernel<<<(Bsz*Cc*Nn)/256, 256>>>(Fs, Ff);

    size_t proj_smem = (size_t)PROJ_SMEM_HALFS * sizeof(__half);
    cudaFuncSetAttribute(proj_kernel, cudaFuncAttributeMaxDynamicSharedMemorySize, (int)proj_smem);
    proj_kernel<<<dim3(64, Bsz), 128, proj_smem>>>(Wq1, Wk1, Wq2, Wk2, Wv, lam);

    size_t flash_smem = (size_t)FLASH_SMEM_HALFS * sizeof(__half);
    cudaFuncSetAttribute(flash_kernel, cudaFuncAttributeMaxDynamicSharedMemorySize, (int)flash_smem);
    flash_kernel<<<dim3(64, Bsz), 128, flash_smem>>>(Wproj);

    size_t ffn_smem = (size_t)FFN_SMEM_HALFS * sizeof(__half);
    cudaFuncSetAttribute(ffn_kernel, cudaFuncAttributeMaxDynamicSharedMemorySize, (int)ffn_smem);
    ffn_kernel<<<dim3(64, Bsz), 128, ffn_smem>>>(W1, W2);

    bnstats_kernel<<<Cc, 256>>>();
    bnapply_kernel<<<(Bsz*Cc*Nn)/256, 256>>>(gamma, beta, out);
}

// round 4
// speedup vs baseline: 11.2612x; 1.7451x over previous
#include <cuda_runtime.h>
#include <cuda_fp16.h>
#include <math.h>
#include <stdint.h>

// Problem constants
#define Bsz 4
#define Cc  64
#define Nn  4096
#define HIDD 256
#define EPSBN 1e-5f

// ---------------- scratch (__device__ globals; no allocation) ----------------
__device__ float  gFl [Bsz*Cc*Nn];     // Fs+Ff, channel-major (fp32, exact residual)
__device__ __half gQ  [Bsz*Nn*128];    // [0.125*q1 | -0.125*lam*q2], token-major
__device__ __half gK  [Bsz*Nn*128];    // [k1 | k2], token-major
__device__ __half gVT [Bsz*Cc*Nn];     // v, d-major [B][D][N]
__device__ __half gO  [Bsz*Nn*Cc];     // Wproj @ attention-out, token-major
__device__ float  gY  [Bsz*Cc*Nn];     // FFN output, channel-major
__device__ float  gBNsum[2*Cc];        // per-channel sum / sumsq accumulators

// fp16 weight caches (filled by prep kernel each launch)
__device__ __half gWqk[5*4096];        // q1,k1,q2,k2,v  (scales folded into q1,q2)
__device__ __half gWp [4096];
__device__ __half gW1h[HIDD*Cc];
__device__ __half gW2h[Cc*HIDD];

// ---------------- mma m16n8k16 fp16 in / fp32 accum ----------------
__device__ __forceinline__ void mma_f16(float* c, const uint32_t* a, uint32_t b0, uint32_t b1) {
    asm volatile(
        "mma.sync.aligned.m16n8k16.row.col.f32.f16.f16.f32 "
        "{%0,%1,%2,%3}, {%4,%5,%6,%7}, {%8,%9}, {%0,%1,%2,%3};"
        : "+f"(c[0]), "+f"(c[1]), "+f"(c[2]), "+f"(c[3])
        : "r"(a[0]), "r"(a[1]), "r"(a[2]), "r"(a[3]), "r"(b0), "r"(b1));
}

__device__ __forceinline__ uint32_t pack2(float x, float y) {
    __half2 h = __floats2half2_rn(x, y);
    return *(uint32_t*)&h;
}

__device__ __forceinline__ void cp16(void* s, const void* g) {
    uint32_t sa = (uint32_t)__cvta_generic_to_shared(s);
    asm volatile("cp.async.cg.shared.global [%0], [%1], 16;" :: "r"(sa), "l"(g));
}

// ---------------- K0: weight prep (fp32->fp16, scales folded) + BN acc zero ----------------
__global__ void prep_kernel(const float* __restrict__ Wq1, const float* __restrict__ Wk1,
                            const float* __restrict__ Wq2, const float* __restrict__ Wk2,
                            const float* __restrict__ Wv,  const float* __restrict__ Wproj,
                            const float* __restrict__ W1,  const float* __restrict__ W2,
                            const float* __restrict__ lam_p)
{
    int idx = blockIdx.x * blockDim.x + threadIdx.x;
    if (idx < 128) gBNsum[idx] = 0.f;
    if (idx < 20480) {
        int m = idx >> 12, r = idx & 4095;
        const float* src[5] = {Wq1, Wk1, Wq2, Wk2, Wv};
        float scl = (m == 0) ? 0.125f : (m == 2) ? -0.125f * __ldg(lam_p) : 1.0f;
        gWqk[idx] = __float2half(src[m][r] * scl);
    } else if (idx < 24576) {
        gWp[idx - 20480] = __float2half(Wproj[idx - 20480]);
    } else if (idx < 40960) {
        gW1h[idx - 24576] = __float2half(W1[idx - 24576]);
    } else {
        gW2h[idx - 40960] = __float2half(W2[idx - 40960]);
    }
}

// ---------------- K1: fused add + 5 input projections ----------------
// Block = 128 tokens, 256 threads / 8 warps, each warp owns 16 token rows.
#define XS_LD 66
#define WS_LD 72
#define PROJ_SMEM_HALFS (128*XS_LD + 320*WS_LD)

__global__ void __launch_bounds__(256) proj_kernel(
    const float* __restrict__ Fs, const float* __restrict__ Ff)
{
    extern __shared__ __half sh[];
    __half* xs = sh;                 // [128 tok][66]
    __half* ws = sh + 128*XS_LD;     // [320 rows][72]

    int b  = blockIdx.y;
    int n0 = blockIdx.x << 7;
    int t  = threadIdx.x;
    int w = t >> 5, lane = t & 31, g = lane >> 2, t4 = lane & 3;

    // fused add: Fl = Fs+Ff, write residual + stage fp16 token-major
    for (int idx = t; idx < 8192; idx += 256) {
        int c = idx >> 7, n = idx & 127;
        size_t gi = (size_t)((b<<6) + c)*Nn + n0 + n;
        float v = Fs[gi] + Ff[gi];
        gFl[gi] = v;
        xs[n*XS_LD + c] = __float2half(v);
    }
    // stage all 5 weight matrices (fp16, uint4 copies)
    for (int idx = t; idx < 2560; idx += 256) {
        int r = idx >> 3, ch = idx & 7;
        *(uint4*)&ws[r*WS_LD + ch*8] = ((const uint4*)gWqk)[r*8 + ch];
    }
    __syncthreads();

    int row0 = w*16 + g;

    uint32_t xa[4][4];
    #pragma unroll
    for (int ks = 0; ks < 4; ks++) {
        xa[ks][0] = *(uint32_t*)&xs[ row0     *XS_LD + 16*ks + 2*t4];
        xa[ks][1] = *(uint32_t*)&xs[(row0 + 8)*XS_LD + 16*ks + 2*t4];
        xa[ks][2] = *(uint32_t*)&xs[ row0     *XS_LD + 16*ks + 2*t4 + 8];
        xa[ks][3] = *(uint32_t*)&xs[(row0 + 8)*XS_LD + 16*ks + 2*t4 + 8];
    }

    for (int m = 0; m < 5; m++) {
        float acc[8][4];
        #pragma unroll
        for (int nt = 0; nt < 8; nt++)
            acc[nt][0] = acc[nt][1] = acc[nt][2] = acc[nt][3] = 0.f;

        const __half* wm = ws + m*64*WS_LD;
        #pragma unroll
        for (int nt = 0; nt < 8; nt++) {
            const __half* wrow = wm + (nt*8 + g)*WS_LD;
            #pragma unroll
            for (int ks = 0; ks < 4; ks++) {
                uint32_t b0 = *(uint32_t*)&wrow[16*ks + 2*t4];
                uint32_t b1 = *(uint32_t*)&wrow[16*ks + 2*t4 + 8];
                mma_f16(acc[nt], xa[ks], b0, b1);
            }
        }

        if (m == 4) {
            #pragma unroll
            for (int nt = 0; nt < 8; nt++) {
                int d0 = nt*8 + 2*t4;
                gVT[((b<<6) + d0    )*Nn + n0 + row0    ] = __float2half(acc[nt][0]);
                gVT[((b<<6) + d0 + 1)*Nn + n0 + row0    ] = __float2half(acc[nt][1]);
                gVT[((b<<6) + d0    )*Nn + n0 + row0 + 8] = __float2half(acc[nt][2]);
                gVT[((b<<6) + d0 + 1)*Nn + n0 + row0 + 8] = __float2half(acc[nt][3]);
            }
        } else {
            __half* dst = (m == 0 || m == 2) ? gQ : gK;
            int off = (m >= 2) ? 64 : 0;
            #pragma unroll
            for (int nt = 0; nt < 8; nt++) {
                *(uint32_t*)&dst[(size_t)(b*Nn + n0 + row0    )*128 + off + nt*8 + 2*t4]
                    = pack2(acc[nt][0], acc[nt][1]);
                *(uint32_t*)&dst[(size_t)(b*Nn + n0 + row0 + 8)*128 + off + nt*8 + 2*t4]
                    = pack2(acc[nt][2], acc[nt][3]);
            }
        }
    }
}

// ---------------- K2: flash attention + fused Wproj, cp.async double-buffered ----------------
// Block = 128 queries, 256 threads / 8 warps x 16 rows. K-tile = 64 keys.
#define KS_LD 136
#define VT_LD 72
#define WP_LD 72
#define KBUF (64*KS_LD)
#define VBUF (64*VT_LD)
#define FLASH_SMEM_HALFS (2*KBUF + 2*VBUF + 64*WP_LD)

__global__ void __launch_bounds__(256) flash_kernel()
{
    extern __shared__ __half sh[];
    __half* ks  = sh;                      // double buffer; also Q staging (128 rows)
    __half* vs  = sh + 2*KBUF;             // double buffer
    __half* wp  = sh + 2*KBUF + 2*VBUF;    // Wproj [64][72]

    int b  = blockIdx.y;
    int q0 = blockIdx.x << 7;
    int t  = threadIdx.x;
    int w = t >> 5, lane = t & 31, g = lane >> 2, t4 = lane & 3;
    int row0 = w*16 + g, row1 = row0 + 8;

    // stage Wproj (fp16 copy)
    for (int idx = t; idx < 512; idx += 256) {
        int c = idx >> 3, ch = idx & 7;
        *(uint4*)&wp[c*WP_LD + ch*8] = ((const uint4*)gWp)[c*8 + ch];
    }
    // stage Q tile (128 rows) through ks region
    const uint4* Qg = (const uint4*)(gQ + (size_t)(b*Nn + q0)*128);
    for (int idx = t; idx < 2048; idx += 256) {
        int r = idx >> 4, ch = idx & 15;
        *(uint4*)&ks[r*KS_LD + ch*8] = Qg[r*16 + ch];
    }
    __syncthreads();

    uint32_t qa[8][4];
    #pragma unroll
    for (int kst = 0; kst < 8; kst++) {
        qa[kst][0] = *(uint32_t*)&ks[row0*KS_LD + 16*kst + 2*t4];
        qa[kst][1] = *(uint32_t*)&ks[row1*KS_LD + 16*kst + 2*t4];
        qa[kst][2] = *(uint32_t*)&ks[row0*KS_LD + 16*kst + 2*t4 + 8];
        qa[kst][3] = *(uint32_t*)&ks[row1*KS_LD + 16*kst + 2*t4 + 8];
    }
    __syncthreads();   // Q frags in regs; ks buffers free for K tiles

    float oc[8][4];
    #pragma unroll
    for (int nt = 0; nt < 8; nt++)
        oc[nt][0] = oc[nt][1] = oc[nt][2] = oc[nt][3] = 0.f;
    float m0 = -1e30f, m1 = -1e30f, l0 = 0.f, l1 = 0.f;

    const uint4* Kg = (const uint4*)(gK  + (size_t)b*Nn*128);
    const uint4* Vg = (const uint4*)(gVT + (size_t)b*64*Nn);

    // prefetch tile 0 into buffer 0
    {
        __half* kd = ks; __half* vd = vs;
        for (int idx = t; idx < 1024; idx += 256) {
            int r = idx >> 4, ch = idx & 15;
            cp16(&kd[r*KS_LD + ch*8], &Kg[r*16 + ch]);
        }
        for (int idx = t; idx < 512; idx += 256) {
            int d = idx >> 3, ch = idx & 7;
            cp16(&vd[d*VT_LD + ch*8], &Vg[d*512 + ch]);
        }
        asm volatile("cp.async.commit_group;");
    }

    for (int kt = 0; kt < 64; kt++) {
        __half* kc = ks + (kt & 1)*KBUF;
        __half* vc = vs + (kt & 1)*VBUF;

        if (kt + 1 < 64) {
            __half* kd = ks + ((kt + 1) & 1)*KBUF;
            __half* vd = vs + ((kt + 1) & 1)*VBUF;
            int kt0 = (kt + 1) << 6;
            for (int idx = t; idx < 1024; idx += 256) {
                int r = idx >> 4, ch = idx & 15;
                cp16(&kd[r*KS_LD + ch*8], &Kg[(kt0 + r)*16 + ch]);
            }
            for (int idx = t; idx < 512; idx += 256) {
                int d = idx >> 3, ch = idx & 7;
                cp16(&vd[d*VT_LD + ch*8], &Vg[d*512 + (kt0 >> 3) + ch]);
            }
            asm volatile("cp.async.commit_group;");
            asm volatile("cp.async.wait_group 1;");
        } else {
            asm volatile("cp.async.wait_group 0;");
        }
        __syncthreads();

        // ---- S = Q K^T ----
        float sc[8][4];
        #pragma unroll
        for (int nt = 0; nt < 8; nt++) {
            sc[nt][0] = sc[nt][1] = sc[nt][2] = sc[nt][3] = 0.f;
            const __half* kb = &kc[(nt*8 + g)*KS_LD];
            #pragma unroll
            for (int kst = 0; kst < 8; kst++) {
                uint32_t b0 = *(uint32_t*)&kb[16*kst + 2*t4];
                uint32_t b1 = *(uint32_t*)&kb[16*kst + 2*t4 + 8];
                mma_f16(sc[nt], qa[kst], b0, b1);
            }
        }

        // ---- online softmax ----
        float mx0 = -1e30f, mx1 = -1e30f;
        #pragma unroll
        for (int nt = 0; nt < 8; nt++) {
            mx0 = fmaxf(mx0, fmaxf(sc[nt][0], sc[nt][1]));
            mx1 = fmaxf(mx1, fmaxf(sc[nt][2], sc[nt][3]));
        }
        mx0 = fmaxf(mx0, __shfl_xor_sync(0xffffffffu, mx0, 1));
        mx0 = fmaxf(mx0, __shfl_xor_sync(0xffffffffu, mx0, 2));
        mx1 = fmaxf(mx1, __shfl_xor_sync(0xffffffffu, mx1, 1));
        mx1 = fmaxf(mx1, __shfl_xor_sync(0xffffffffu, mx1, 2));

        float mn0 = fmaxf(m0, mx0), mn1 = fmaxf(m1, mx1);
        float cr0 = __expf(m0 - mn0), cr1 = __expf(m1 - mn1);
        m0 = mn0; m1 = mn1;

        float sum0 = 0.f, sum1 = 0.f;
        #pragma unroll
        for (int nt = 0; nt < 8; nt++) {
            sc[nt][0] = __expf(sc[nt][0] - mn0);
            sc[nt][1] = __expf(sc[nt][1] - mn0);
            sc[nt][2] = __expf(sc[nt][2] - mn1);
            sc[nt][3] = __expf(sc[nt][3] - mn1);
            sum0 += sc[nt][0] + sc[nt][1];
            sum1 += sc[nt][2] + sc[nt][3];
            oc[nt][0] *= cr0; oc[nt][1] *= cr0;
            oc[nt][2] *= cr1; oc[nt][3] *= cr1;
        }
        sum0 += __shfl_xor_sync(0xffffffffu, sum0, 1);
        sum0 += __shfl_xor_sync(0xffffffffu, sum0, 2);
        sum1 += __shfl_xor_sync(0xffffffffu, sum1, 1);
        sum1 += __shfl_xor_sync(0xffffffffu, sum1, 2);
        l0 = l0*cr0 + sum0;
        l1 = l1*cr1 + sum1;

        // ---- pack P, O += P V ----
        uint32_t pa[4][4];
        #pragma unroll
        for (int kst = 0; kst < 4; kst++) {
            pa[kst][0] = pack2(sc[2*kst  ][0], sc[2*kst  ][1]);
            pa[kst][1] = pack2(sc[2*kst  ][2], sc[2*kst  ][3]);
            pa[kst][2] = pack2(sc[2*kst+1][0], sc[2*kst+1][1]);
            pa[kst][3] = pack2(sc[2*kst+1][2], sc[2*kst+1][3]);
        }
        #pragma unroll
        for (int nt = 0; nt < 8; nt++) {
            const __half* vb = &vc[(nt*8 + g)*VT_LD];
            #pragma unroll
            for (int kst = 0; kst < 4; kst++) {
                uint32_t b0 = *(uint32_t*)&vb[16*kst + 2*t4];
                uint32_t b1 = *(uint32_t*)&vb[16*kst + 2*t4 + 8];
                mma_f16(oc[nt], pa[kst], b0, b1);
            }
        }
        __syncthreads();   // reads of buffer done before its next cp.async overwrite
    }

    // ---- normalize + fused output projection ----
    float inv0 = 1.f / l0, inv1 = 1.f / l1;
    uint32_t oa[4][4];
    #pragma unroll
    for (int kst = 0; kst < 4; kst++) {
        oa[kst][0] = pack2(oc[2*kst  ][0]*inv0, oc[2*kst  ][1]*inv0);
        oa[kst][1] = pack2(oc[2*kst  ][2]*inv1, oc[2*kst  ][3]*inv1);
        oa[kst][2] = pack2(oc[2*kst+1][0]*inv0, oc[2*kst+1][1]*inv0);
        oa[kst][3] = pack2(oc[2*kst+1][2]*inv1, oc[2*kst+1][3]*inv1);
    }
    float po[8][4];
    #pragma unroll
    for (int nt = 0; nt < 8; nt++) {
        po[nt][0] = po[nt][1] = po[nt][2] = po[nt][3] = 0.f;
        const __half* wrow = &wp[(nt*8 + g)*WP_LD];
        #pragma unroll
        for (int kst = 0; kst < 4; kst++) {
            uint32_t b0 = *(uint32_t*)&wrow[16*kst + 2*t4];
            uint32_t b1 = *(uint32_t*)&wrow[16*kst + 2*t4 + 8];
            mma_f16(po[nt], oa[kst], b0, b1);
        }
    }
    #pragma unroll
    for (int nt = 0; nt < 8; nt++) {
        *(uint32_t*)&gO[(size_t)(b*Nn + q0 + row0)*64 + nt*8 + 2*t4] = pack2(po[nt][0], po[nt][1]);
        *(uint32_t*)&gO[(size_t)(b*Nn + q0 + row1)*64 + nt*8 + 2*t4] = pack2(po[nt][2], po[nt][3]);
    }
}

// ---------------- K3: FFN + fused BN partial sums ----------------
#define OS_LD 72
#define W1_LD 72
#define W2_LD 264
#define YS_LD 132
#define FFN_SMEM_HALFS (128*OS_LD + HIDD*W1_LD + 64*W2_LD)

__global__ void __launch_bounds__(256) ffn_kernel()
{
    extern __shared__ __half sh[];
    __half* os  = sh;                       // [128 tok][72]
    __half* w1s = sh + 128*OS_LD;           // [256 e][72]
    __half* w2s = w1s + HIDD*W1_LD;         // [64 c][264]

    int b  = blockIdx.y;
    int n0 = blockIdx.x << 7;
    int t  = threadIdx.x;
    int w = t >> 5, lane = t & 31, g = lane >> 2, t4 = lane & 3;
    int row0 = w*16 + g;

    const uint4* Og = (const uint4*)(gO + (size_t)(b*Nn + n0)*64);
    for (int idx = t; idx < 1024; idx += 256) {
        int r = idx >> 3, ch = idx & 7;
        *(uint4*)&os[r*OS_LD + ch*8] = Og[r*8 + ch];
    }
    for (int idx = t; idx < 2048; idx += 256) {
        int e = idx >> 3, ch = idx & 7;
        *(uint4*)&w1s[e*W1_LD + ch*8] = ((const uint4*)gW1h)[e*8 + ch];
    }
    for (int idx = t; idx < 2048; idx += 256) {
        int c = idx >> 5, ch = idx & 31;
        *(uint4*)&w2s[c*W2_LD + ch*8] = ((const uint4*)gW2h)[c*32 + ch];
    }
    __syncthreads();

    uint32_t oa[4][4];
    #pragma unroll
    for (int ks = 0; ks < 4; ks++) {
        oa[ks][0] = *(uint32_t*)&os[ row0     *OS_LD + 16*ks + 2*t4];
        oa[ks][1] = *(uint32_t*)&os[(row0 + 8)*OS_LD + 16*ks + 2*t4];
        oa[ks][2] = *(uint32_t*)&os[ row0     *OS_LD + 16*ks + 2*t4 + 8];
        oa[ks][3] = *(uint32_t*)&os[(row0 + 8)*OS_LD + 16*ks + 2*t4 + 8];
    }

    float yacc[8][4];
    #pragma unroll
    for (int nt = 0; nt < 8; nt++)
        yacc[nt][0] = yacc[nt][1] = yacc[nt][2] = yacc[nt][3] = 0.f;

    for (int ch = 0; ch < 4; ch++) {
        float hacc[8][4];
        #pragma unroll
        for (int nt = 0; nt < 8; nt++) {
            hacc[nt][0] = hacc[nt][1] = hacc[nt][2] = hacc[nt][3] = 0.f;
            const __half* wrow = &w1s[(ch*64 + nt*8 + g)*W1_LD];
            #pragma unroll
            for (int ks = 0; ks < 4; ks++) {
                uint32_t b0 = *(uint32_t*)&wrow[16*ks + 2*t4];
                uint32_t b1 = *(uint32_t*)&wrow[16*ks + 2*t4 + 8];
                mma_f16(hacc[nt], oa[ks], b0, b1);
            }
        }
        #pragma unroll
        for (int nt = 0; nt < 8; nt++)
            #pragma unroll
            for (int j = 0; j < 4; j++) {
                float v = hacc[nt][j];
                hacc[nt][j] = 0.5f * v * (1.f + erff(v * 0.70710678118654752f));
            }
        uint32_t ha[4][4];
        #pragma unroll
        for (int kst = 0; kst < 4; kst++) {
            ha[kst][0] = pack2(hacc[2*kst  ][0], hacc[2*kst  ][1]);
            ha[kst][1] = pack2(hacc[2*kst  ][2], hacc[2*kst  ][3]);
            ha[kst][2] = pack2(hacc[2*kst+1][0], hacc[2*kst+1][1]);
            ha[kst][3] = pack2(hacc[2*kst+1][2], hacc[2*kst+1][3]);
        }
        #pragma unroll
        for (int nt = 0; nt < 8; nt++) {
            const __half* wrow = &w2s[(nt*8 + g)*W2_LD + ch*64];
            #pragma unroll
            for (int kst = 0; kst < 4; kst++) {
                uint32_t b0 = *(uint32_t*)&wrow[16*kst + 2*t4];
                uint32_t b1 = *(uint32_t*)&wrow[16*kst + 2*t4 + 8];
                mma_f16(yacc[nt], ha[kst], b0, b1);
            }
        }
    }
    __syncthreads();   // smem reads done; reuse as fp32 transpose buffer

    float* ys = (float*)sh;   // [64 c][132]
    #pragma unroll
    for (int nt = 0; nt < 8; nt++) {
        int c0 = nt*8 + 2*t4;
        ys[ c0     *YS_LD + row0    ] = yacc[nt][0];
        ys[(c0 + 1)*YS_LD + row0    ] = yacc[nt][1];
        ys[ c0     *YS_LD + row0 + 8] = yacc[nt][2];
        ys[(c0 + 1)*YS_LD + row0 + 8] = yacc[nt][3];
    }
    __syncthreads();

    // coalesced gY store
    for (int idx = t; idx < 8192; idx += 256) {
        int c = idx >> 7, n = idx & 127;
        gY[((b<<6) + c)*Nn + n0 + n] = ys[c*YS_LD + n];
    }
    // fused BN partials: one channel per thread (t<64), staggered start (conflict-free)
    if (t < 64) {
        int c = t;
        float s = 0.f, s2 = 0.f;
        for (int j = 0; j < 128; j++) {
            int n = (j + c) & 127;
            float v = ys[c*YS_LD + n];
            s += v; s2 = fmaf(v, v, s2);
        }
        atomicAdd(&gBNsum[c], s);
        atomicAdd(&gBNsum[64 + c], s2);
    }
}

// ---------------- K4: apply BN + residual ----------------
__global__ void bnapply_kernel(const float* __restrict__ gamma,
                               const float* __restrict__ beta,
                               float* __restrict__ out)
{
    int i = blockIdx.x * blockDim.x + threadIdx.x;
    int c = (i >> 12) & 63;
    const float invN = 1.f / (Bsz * Nn);
    float mean = gBNsum[c] * invN;
    float var  = gBNsum[64 + c] * invN - mean*mean;
    float is   = rsqrtf(var + EPSBN);
    out[i] = (gY[i] - mean) * is * gamma[c] + beta[c] + gFl[i];
}

// ---------------- launch ----------------
extern "C" void kernel_launch(void* const* d_in, const int* in_sizes, int n_in,
                              void* d_out, int out_size)
{
    const float* Fs    = (const float*)d_in[0];
    const float* Ff    = (const float*)d_in[1];
    const float* Wq1   = (const float*)d_in[2];
    const float* Wk1   = (const float*)d_in[3];
    const float* Wq2   = (const float*)d_in[4];
    const float* Wk2   = (const float*)d_in[5];
    const float* Wv    = (const float*)d_in[6];
    const float* Wproj = (const float*)d_in[7];
    const float* W1    = (const float*)d_in[8];
    const float* W2    = (const float*)d_in[9];
    const float* gamma = (const float*)d_in[10];
    const float* beta  = (const float*)d_in[11];
    const float* lam   = (const float*)d_in[12];
    float* out = (float*)d_out;

    prep_kernel<<<224, 256>>>(Wq1, Wk1, Wq2, Wk2, Wv, Wproj, W1, W2, lam);

    size_t proj_smem = (size_t)PROJ_SMEM_HALFS * sizeof(__half);
    cudaFuncSetAttribute(proj_kernel, cudaFuncAttributeMaxDynamicSharedMemorySize, (int)proj_smem);
    proj_kernel<<<dim3(32, Bsz), 256, proj_smem>>>(Fs, Ff);

    size_t flash_smem = (size_t)FLASH_SMEM_HALFS * sizeof(__half);
    cudaFuncSetAttribute(flash_kernel, cudaFuncAttributeMaxDynamicSharedMemorySize, (int)flash_smem);
    flash_kernel<<<dim3(32, Bsz), 256, flash_smem>>>();

    size_t ffn_smem = (size_t)FFN_SMEM_HALFS * sizeof(__half);
    cudaFuncSetAttribute(ffn_kernel, cudaFuncAttributeMaxDynamicSharedMemorySize, (int)ffn_smem);
    ffn_kernel<<<dim3(32, Bsz), 256, ffn_smem>>>();

    bnapply_kernel<<<(Bsz*Cc*Nn)/256, 256>>>(gamma, beta, out);
}

// round 5
// speedup vs baseline: 12.2230x; 1.0854x over previous
#include <cuda_runtime.h>
#include <cuda_fp16.h>
#include <math.h>
#include <stdint.h>

// Problem constants
#define Bsz 4
#define Cc  64
#define Nn  4096
#define HIDD 256
#define EPSBN 1e-5f
#define LOG2E 1.44269504088896340736f

// ---------------- scratch (__device__ globals; no allocation) ----------------
__device__ float  gFl [Bsz*Cc*Nn];     // Fs+Ff, channel-major (fp32, exact residual)
__device__ __half gQ  [Bsz*Nn*128];    // [0.125*log2e*q1 | -0.125*lam*log2e*q2], token-major
__device__ __half gK  [Bsz*Nn*128];    // [k1 | k2], token-major
__device__ __half gVT [Bsz*Cc*Nn];     // v, d-major [B][D][N]
__device__ __half gO  [Bsz*Nn*Cc];     // Wproj @ attention-out, token-major
__device__ float  gY  [Bsz*Cc*Nn];     // FFN output, channel-major
__device__ float  gBNsum[2*Cc];        // per-channel sum / sumsq accumulators

// fp16 weight caches (filled by prep kernel each launch)
__device__ __half gWqk[5*4096];        // q1,k1,q2,k2,v  (scales folded into q1,q2)
__device__ __half gWp [4096];
__device__ __half gW1h[HIDD*Cc];
__device__ __half gW2h[Cc*HIDD];

// ---------------- mma / ldmatrix helpers ----------------
__device__ __forceinline__ void mma_f16(float* c, const uint32_t* a, uint32_t b0, uint32_t b1) {
    asm volatile(
        "mma.sync.aligned.m16n8k16.row.col.f32.f16.f16.f32 "
        "{%0,%1,%2,%3}, {%4,%5,%6,%7}, {%8,%9}, {%0,%1,%2,%3};"
        : "+f"(c[0]), "+f"(c[1]), "+f"(c[2]), "+f"(c[3])
        : "r"(a[0]), "r"(a[1]), "r"(a[2]), "r"(a[3]), "r"(b0), "r"(b1));
}

// 4x 8x8 b16 matrices; lane l supplies the row address it was given.
__device__ __forceinline__ void ldsm_x4(uint32_t* r, const __half* p) {
    uint32_t addr = (uint32_t)__cvta_generic_to_shared(p);
    asm volatile("ldmatrix.sync.aligned.m8n8.x4.shared.b16 {%0,%1,%2,%3}, [%4];"
        : "=r"(r[0]), "=r"(r[1]), "=r"(r[2]), "=r"(r[3]) : "r"(addr));
}

__device__ __forceinline__ uint32_t pack2(float x, float y) {
    __half2 h = __floats2half2_rn(x, y);
    return *(uint32_t*)&h;
}

__device__ __forceinline__ float ex2(float x) {
    float r; asm("ex2.approx.f32 %0, %1;" : "=f"(r) : "f"(x)); return r;
}

__device__ __forceinline__ void cp16(void* s, const void* g) {
    uint32_t sa = (uint32_t)__cvta_generic_to_shared(s);
    asm volatile("cp.async.cg.shared.global [%0], [%1], 16;" :: "r"(sa), "l"(g));
}

// ---------------- K0: weight prep (fp32->fp16, scales folded) + BN acc zero ----------------
__global__ void prep_kernel(const float* __restrict__ Wq1, const float* __restrict__ Wk1,
                            const float* __restrict__ Wq2, const float* __restrict__ Wk2,
                            const float* __restrict__ Wv,  const float* __restrict__ Wproj,
                            const float* __restrict__ W1,  const float* __restrict__ W2,
                            const float* __restrict__ lam_p)
{
    int idx = blockIdx.x * blockDim.x + threadIdx.x;
    if (idx < 128) gBNsum[idx] = 0.f;
    if (idx < 20480) {
        int m = idx >> 12, r = idx & 4095;
        const float* src[5] = {Wq1, Wk1, Wq2, Wk2, Wv};
        float scl = (m == 0) ? 0.125f*LOG2E : (m == 2) ? -0.125f*LOG2E * __ldg(lam_p) : 1.0f;
        gWqk[idx] = __float2half(src[m][r] * scl);
    } else if (idx < 24576) {
        gWp[idx - 20480] = __float2half(Wproj[idx - 20480]);
    } else if (idx < 40960) {
        gW1h[idx - 24576] = __float2half(W1[idx - 24576]);
    } else {
        gW2h[idx - 40960] = __float2half(W2[idx - 40960]);
    }
}

// ---------------- K1: fused add + 5 input projections ----------------
#define XS_LD 66
#define WS_LD 72
#define PROJ_SMEM_HALFS (128*XS_LD + 320*WS_LD)

__global__ void __launch_bounds__(256) proj_kernel(
    const float* __restrict__ Fs, const float* __restrict__ Ff)
{
    extern __shared__ __half sh[];
    __half* xs = sh;                 // [128 tok][66]
    __half* ws = sh + 128*XS_LD;     // [320 rows][72]

    int b  = blockIdx.y;
    int n0 = blockIdx.x << 7;
    int t  = threadIdx.x;
    int w = t >> 5, lane = t & 31, g = lane >> 2, t4 = lane & 3;
    int lrow = lane & 7, lcol = (lane >> 3) * 8;

    for (int idx = t; idx < 8192; idx += 256) {
        int c = idx >> 7, n = idx & 127;
        size_t gi = (size_t)((b<<6) + c)*Nn + n0 + n;
        float v = Fs[gi] + Ff[gi];
        gFl[gi] = v;
        xs[n*XS_LD + c] = __float2half(v);
    }
    for (int idx = t; idx < 2560; idx += 256) {
        int r = idx >> 3, ch = idx & 7;
        *(uint4*)&ws[r*WS_LD + ch*8] = ((const uint4*)gWqk)[r*8 + ch];
    }
    __syncthreads();

    int row0 = w*16 + g;

    uint32_t xa[4][4];
    #pragma unroll
    for (int ks = 0; ks < 4; ks++) {
        xa[ks][0] = *(uint32_t*)&xs[ row0     *XS_LD + 16*ks + 2*t4];
        xa[ks][1] = *(uint32_t*)&xs[(row0 + 8)*XS_LD + 16*ks + 2*t4];
        xa[ks][2] = *(uint32_t*)&xs[ row0     *XS_LD + 16*ks + 2*t4 + 8];
        xa[ks][3] = *(uint32_t*)&xs[(row0 + 8)*XS_LD + 16*ks + 2*t4 + 8];
    }

    for (int m = 0; m < 5; m++) {
        float acc[8][4];
        #pragma unroll
        for (int nt = 0; nt < 8; nt++)
            acc[nt][0] = acc[nt][1] = acc[nt][2] = acc[nt][3] = 0.f;

        #pragma unroll
        for (int nt = 0; nt < 8; nt++) {
            const __half* wb = ws + (m*64 + nt*8 + lrow)*WS_LD + lcol;
            #pragma unroll
            for (int ks2 = 0; ks2 < 2; ks2++) {
                uint32_t bb[4];
                ldsm_x4(bb, wb + 32*ks2);
                mma_f16(acc[nt], xa[2*ks2],     bb[0], bb[1]);
                mma_f16(acc[nt], xa[2*ks2 + 1], bb[2], bb[3]);
            }
        }

        if (m == 4) {
            #pragma unroll
            for (int nt = 0; nt < 8; nt++) {
                int d0 = nt*8 + 2*t4;
                gVT[((b<<6) + d0    )*Nn + n0 + row0    ] = __float2half(acc[nt][0]);
                gVT[((b<<6) + d0 + 1)*Nn + n0 + row0    ] = __float2half(acc[nt][1]);
                gVT[((b<<6) + d0    )*Nn + n0 + row0 + 8] = __float2half(acc[nt][2]);
                gVT[((b<<6) + d0 + 1)*Nn + n0 + row0 + 8] = __float2half(acc[nt][3]);
            }
        } else {
            __half* dst = (m == 0 || m == 2) ? gQ : gK;
            int off = (m >= 2) ? 64 : 0;
            #pragma unroll
            for (int nt = 0; nt < 8; nt++) {
                *(uint32_t*)&dst[(size_t)(b*Nn + n0 + row0    )*128 + off + nt*8 + 2*t4]
                    = pack2(acc[nt][0], acc[nt][1]);
                *(uint32_t*)&dst[(size_t)(b*Nn + n0 + row0 + 8)*128 + off + nt*8 + 2*t4]
                    = pack2(acc[nt][2], acc[nt][3]);
            }
        }
    }
}

// ---------------- K2: flash attention + fused Wproj, cp.async + ldmatrix ----------------
#define KS_LD 136
#define VT_LD 72
#define WP_LD 72
#define KBUF (64*KS_LD)
#define VBUF (64*VT_LD)
#define FLASH_SMEM_HALFS (2*KBUF + 2*VBUF + 64*WP_LD)

__global__ void __launch_bounds__(256) flash_kernel()
{
    extern __shared__ __half sh[];
    __half* ks  = sh;
    __half* vs  = sh + 2*KBUF;
    __half* wp  = sh + 2*KBUF + 2*VBUF;

    int b  = blockIdx.y;
    int q0 = blockIdx.x << 7;
    int t  = threadIdx.x;
    int w = t >> 5, lane = t & 31, g = lane >> 2, t4 = lane & 3;
    int row0 = w*16 + g, row1 = row0 + 8;
    int lrow = lane & 7, lcol = (lane >> 3) * 8;

    for (int idx = t; idx < 512; idx += 256) {
        int c = idx >> 3, ch = idx & 7;
        *(uint4*)&wp[c*WP_LD + ch*8] = ((const uint4*)gWp)[c*8 + ch];
    }
    const uint4* Qg = (const uint4*)(gQ + (size_t)(b*Nn + q0)*128);
    for (int idx = t; idx < 2048; idx += 256) {
        int r = idx >> 4, ch = idx & 15;
        *(uint4*)&ks[r*KS_LD + ch*8] = Qg[r*16 + ch];
    }
    __syncthreads();

    uint32_t qa[8][4];
    #pragma unroll
    for (int kst = 0; kst < 8; kst++) {
        qa[kst][0] = *(uint32_t*)&ks[row0*KS_LD + 16*kst + 2*t4];
        qa[kst][1] = *(uint32_t*)&ks[row1*KS_LD + 16*kst + 2*t4];
        qa[kst][2] = *(uint32_t*)&ks[row0*KS_LD + 16*kst + 2*t4 + 8];
        qa[kst][3] = *(uint32_t*)&ks[row1*KS_LD + 16*kst + 2*t4 + 8];
    }
    __syncthreads();

    float oc[8][4];
    #pragma unroll
    for (int nt = 0; nt < 8; nt++)
        oc[nt][0] = oc[nt][1] = oc[nt][2] = oc[nt][3] = 0.f;
    float m0 = -1e30f, m1 = -1e30f, l0 = 0.f, l1 = 0.f;

    const uint4* Kg = (const uint4*)(gK  + (size_t)b*Nn*128);
    const uint4* Vg = (const uint4*)(gVT + (size_t)b*64*Nn);

    {
        __half* kd = ks; __half* vd = vs;
        for (int idx = t; idx < 1024; idx += 256) {
            int r = idx >> 4, ch = idx & 15;
            cp16(&kd[r*KS_LD + ch*8], &Kg[r*16 + ch]);
        }
        for (int idx = t; idx < 512; idx += 256) {
            int d = idx >> 3, ch = idx & 7;
            cp16(&vd[d*VT_LD + ch*8], &Vg[d*512 + ch]);
        }
        asm volatile("cp.async.commit_group;");
    }

    for (int kt = 0; kt < 64; kt++) {
        __half* kc = ks + (kt & 1)*KBUF;
        __half* vc = vs + (kt & 1)*VBUF;

        if (kt + 1 < 64) {
            __half* kd = ks + ((kt + 1) & 1)*KBUF;
            __half* vd = vs + ((kt + 1) & 1)*VBUF;
            int kt0 = (kt + 1) << 6;
            for (int idx = t; idx < 1024; idx += 256) {
                int r = idx >> 4, ch = idx & 15;
                cp16(&kd[r*KS_LD + ch*8], &Kg[(kt0 + r)*16 + ch]);
            }
            for (int idx = t; idx < 512; idx += 256) {
                int d = idx >> 3, ch = idx & 7;
                cp16(&vd[d*VT_LD + ch*8], &Vg[d*512 + (kt0 >> 3) + ch]);
            }
            asm volatile("cp.async.commit_group;");
            asm volatile("cp.async.wait_group 1;");
        } else {
            asm volatile("cp.async.wait_group 0;");
        }
        __syncthreads();

        // ---- S = Q K^T  (ldmatrix B-frags) ----
        float sc[8][4];
        #pragma unroll
        for (int nt = 0; nt < 8; nt++) {
            sc[nt][0] = sc[nt][1] = sc[nt][2] = sc[nt][3] = 0.f;
            const __half* kb = &kc[(nt*8 + lrow)*KS_LD + lcol];
            #pragma unroll
            for (int kst2 = 0; kst2 < 4; kst2++) {
                uint32_t bb[4];
                ldsm_x4(bb, kb + 32*kst2);
                mma_f16(sc[nt], qa[2*kst2],     bb[0], bb[1]);
                mma_f16(sc[nt], qa[2*kst2 + 1], bb[2], bb[3]);
            }
        }

        // ---- online softmax (log2 domain; scores already scaled by log2e) ----
        float mx0 = -1e30f, mx1 = -1e30f;
        #pragma unroll
        for (int nt = 0; nt < 8; nt++) {
            mx0 = fmaxf(mx0, fmaxf(sc[nt][0], sc[nt][1]));
            mx1 = fmaxf(mx1, fmaxf(sc[nt][2], sc[nt][3]));
        }
        mx0 = fmaxf(mx0, __shfl_xor_sync(0xffffffffu, mx0, 1));
        mx0 = fmaxf(mx0, __shfl_xor_sync(0xffffffffu, mx0, 2));
        mx1 = fmaxf(mx1, __shfl_xor_sync(0xffffffffu, mx1, 1));
        mx1 = fmaxf(mx1, __shfl_xor_sync(0xffffffffu, mx1, 2));

        float mn0 = fmaxf(m0, mx0), mn1 = fmaxf(m1, mx1);
        float cr0 = ex2(m0 - mn0), cr1 = ex2(m1 - mn1);
        m0 = mn0; m1 = mn1;

        float sum0 = 0.f, sum1 = 0.f;
        #pragma unroll
        for (int nt = 0; nt < 8; nt++) {
            sc[nt][0] = ex2(sc[nt][0] - mn0);
            sc[nt][1] = ex2(sc[nt][1] - mn0);
            sc[nt][2] = ex2(sc[nt][2] - mn1);
            sc[nt][3] = ex2(sc[nt][3] - mn1);
            sum0 += sc[nt][0] + sc[nt][1];
            sum1 += sc[nt][2] + sc[nt][3];
            oc[nt][0] *= cr0; oc[nt][1] *= cr0;
            oc[nt][2] *= cr1; oc[nt][3] *= cr1;
        }
        sum0 += __shfl_xor_sync(0xffffffffu, sum0, 1);
        sum0 += __shfl_xor_sync(0xffffffffu, sum0, 2);
        sum1 += __shfl_xor_sync(0xffffffffu, sum1, 1);
        sum1 += __shfl_xor_sync(0xffffffffu, sum1, 2);
        l0 = l0*cr0 + sum0;
        l1 = l1*cr1 + sum1;

        // ---- pack P, O += P V (ldmatrix B-frags) ----
        uint32_t pa[4][4];
        #pragma unroll
        for (int kst = 0; kst < 4; kst++) {
            pa[kst][0] = pack2(sc[2*kst  ][0], sc[2*kst  ][1]);
            pa[kst][1] = pack2(sc[2*kst  ][2], sc[2*kst  ][3]);
            pa[kst][2] = pack2(sc[2*kst+1][0], sc[2*kst+1][1]);
            pa[kst][3] = pack2(sc[2*kst+1][2], sc[2*kst+1][3]);
        }
        #pragma unroll
        for (int nt = 0; nt < 8; nt++) {
            const __half* vb = &vc[(nt*8 + lrow)*VT_LD + lcol];
            #pragma unroll
            for (int kst2 = 0; kst2 < 2; kst2++) {
                uint32_t bb[4];
                ldsm_x4(bb, vb + 32*kst2);
                mma_f16(oc[nt], pa[2*kst2],     bb[0], bb[1]);
                mma_f16(oc[nt], pa[2*kst2 + 1], bb[2], bb[3]);
            }
        }
        __syncthreads();
    }

    // ---- normalize + fused output projection ----
    float inv0 = 1.f / l0, inv1 = 1.f / l1;
    uint32_t oa[4][4];
    #pragma unroll
    for (int kst = 0; kst < 4; kst++) {
        oa[kst][0] = pack2(oc[2*kst  ][0]*inv0, oc[2*kst  ][1]*inv0);
        oa[kst][1] = pack2(oc[2*kst  ][2]*inv1, oc[2*kst  ][3]*inv1);
        oa[kst][2] = pack2(oc[2*kst+1][0]*inv0, oc[2*kst+1][1]*inv0);
        oa[kst][3] = pack2(oc[2*kst+1][2]*inv1, oc[2*kst+1][3]*inv1);
    }
    float po[8][4];
    #pragma unroll
    for (int nt = 0; nt < 8; nt++) {
        po[nt][0] = po[nt][1] = po[nt][2] = po[nt][3] = 0.f;
        const __half* wb = &wp[(nt*8 + lrow)*WP_LD + lcol];
        #pragma unroll
        for (int kst2 = 0; kst2 < 2; kst2++) {
            uint32_t bb[4];
            ldsm_x4(bb, wb + 32*kst2);
            mma_f16(po[nt], oa[2*kst2],     bb[0], bb[1]);
            mma_f16(po[nt], oa[2*kst2 + 1], bb[2], bb[3]);
        }
    }
    #pragma unroll
    for (int nt = 0; nt < 8; nt++) {
        *(uint32_t*)&gO[(size_t)(b*Nn + q0 + row0)*64 + nt*8 + 2*t4] = pack2(po[nt][0], po[nt][1]);
        *(uint32_t*)&gO[(size_t)(b*Nn + q0 + row1)*64 + nt*8 + 2*t4] = pack2(po[nt][2], po[nt][3]);
    }
}

// ---------------- K3: FFN + fused BN partial sums ----------------
#define OS_LD 72
#define W1_LD 72
#define W2_LD 264
#define YS_LD 132
#define FFN_SMEM_HALFS (128*OS_LD + HIDD*W1_LD + 64*W2_LD)

__global__ void __launch_bounds__(256) ffn_kernel()
{
    extern __shared__ __half sh[];
    __half* os  = sh;
    __half* w1s = sh + 128*OS_LD;
    __half* w2s = w1s + HIDD*W1_LD;

    int b  = blockIdx.y;
    int n0 = blockIdx.x << 7;
    int t  = threadIdx.x;
    int w = t >> 5, lane = t & 31, g = lane >> 2, t4 = lane & 3;
    int row0 = w*16 + g;
    int lrow = lane & 7, lcol = (lane >> 3) * 8;

    const uint4* Og = (const uint4*)(gO + (size_t)(b*Nn + n0)*64);
    for (int idx = t; idx < 1024; idx += 256) {
        int r = idx >> 3, ch = idx & 7;
        *(uint4*)&os[r*OS_LD + ch*8] = Og[r*8 + ch];
    }
    for (int idx = t; idx < 2048; idx += 256) {
        int e = idx >> 3, ch = idx & 7;
        *(uint4*)&w1s[e*W1_LD + ch*8] = ((const uint4*)gW1h)[e*8 + ch];
    }
    for (int idx = t; idx < 2048; idx += 256) {
        int c = idx >> 5, ch = idx & 31;
        *(uint4*)&w2s[c*W2_LD + ch*8] = ((const uint4*)gW2h)[c*32 + ch];
    }
    __syncthreads();

    uint32_t oa[4][4];
    #pragma unroll
    for (int ks = 0; ks < 4; ks++) {
        oa[ks][0] = *(uint32_t*)&os[ row0     *OS_LD + 16*ks + 2*t4];
        oa[ks][1] = *(uint32_t*)&os[(row0 + 8)*OS_LD + 16*ks + 2*t4];
        oa[ks][2] = *(uint32_t*)&os[ row0     *OS_LD + 16*ks + 2*t4 + 8];
        oa[ks][3] = *(uint32_t*)&os[(row0 + 8)*OS_LD + 16*ks + 2*t4 + 8];
    }

    float yacc[8][4];
    #pragma unroll
    for (int nt = 0; nt < 8; nt++)
        yacc[nt][0] = yacc[nt][1] = yacc[nt][2] = yacc[nt][3] = 0.f;

    for (int ch = 0; ch < 4; ch++) {
        float hacc[8][4];
        #pragma unroll
        for (int nt = 0; nt < 8; nt++) {
            hacc[nt][0] = hacc[nt][1] = hacc[nt][2] = hacc[nt][3] = 0.f;
            const __half* wb = &w1s[(ch*64 + nt*8 + lrow)*W1_LD + lcol];
            #pragma unroll
            for (int ks2 = 0; ks2 < 2; ks2++) {
                uint32_t bb[4];
                ldsm_x4(bb, wb + 32*ks2);
                mma_f16(hacc[nt], oa[2*ks2],     bb[0], bb[1]);
                mma_f16(hacc[nt], oa[2*ks2 + 1], bb[2], bb[3]);
            }
        }
        #pragma unroll
        for (int nt = 0; nt < 8; nt++)
            #pragma unroll
            for (int j = 0; j < 4; j++) {
                float v = hacc[nt][j];
                hacc[nt][j] = 0.5f * v * (1.f + erff(v * 0.70710678118654752f));
            }
        uint32_t ha[4][4];
        #pragma unroll
        for (int kst = 0; kst < 4; kst++) {
            ha[kst][0] = pack2(hacc[2*kst  ][0], hacc[2*kst  ][1]);
            ha[kst][1] = pack2(hacc[2*kst  ][2], hacc[2*kst  ][3]);
            ha[kst][2] = pack2(hacc[2*kst+1][0], hacc[2*kst+1][1]);
            ha[kst][3] = pack2(hacc[2*kst+1][2], hacc[2*kst+1][3]);
        }
        #pragma unroll
        for (int nt = 0; nt < 8; nt++) {
            const __half* wb = &w2s[(nt*8 + lrow)*W2_LD + ch*64 + lcol];
            #pragma unroll
            for (int kst2 = 0; kst2 < 2; kst2++) {
                uint32_t bb[4];
                ldsm_x4(bb, wb + 32*kst2);
                mma_f16(yacc[nt], ha[2*kst2],     bb[0], bb[1]);
                mma_f16(yacc[nt], ha[2*kst2 + 1], bb[2], bb[3]);
            }
        }
    }
    __syncthreads();

    float* ys = (float*)sh;   // [64 c][132]
    #pragma unroll
    for (int nt = 0; nt < 8; nt++) {
        int c0 = nt*8 + 2*t4;
        ys[ c0     *YS_LD + row0    ] = yacc[nt][0];
        ys[(c0 + 1)*YS_LD + row0    ] = yacc[nt][1];
        ys[ c0     *YS_LD + row0 + 8] = yacc[nt][2];
        ys[(c0 + 1)*YS_LD + row0 + 8] = yacc[nt][3];
    }
    __syncthreads();

    for (int idx = t; idx < 8192; idx += 256) {
        int c = idx >> 7, n = idx & 127;
        gY[((b<<6) + c)*Nn + n0 + n] = ys[c*YS_LD + n];
    }
    if (t < 64) {
        int c = t;
        float s = 0.f, s2 = 0.f;
        for (int j = 0; j < 128; j++) {
            int n = (j + c) & 127;
            float v = ys[c*YS_LD + n];
            s += v; s2 = fmaf(v, v, s2);
        }
        atomicAdd(&gBNsum[c], s);
        atomicAdd(&gBNsum[64 + c], s2);
    }
}

// ---------------- K4: apply BN + residual ----------------
__global__ void bnapply_kernel(const float* __restrict__ gamma,
                               const float* __restrict__ beta,
                               float* __restrict__ out)
{
    int i = blockIdx.x * blockDim.x + threadIdx.x;
    int c = (i >> 12) & 63;
    const float invN = 1.f / (Bsz * Nn);
    float mean = gBNsum[c] * invN;
    float var  = gBNsum[64 + c] * invN - mean*mean;
    float is   = rsqrtf(var + EPSBN);
    out[i] = (gY[i] - mean) * is * gamma[c] + beta[c] + gFl[i];
}

// ---------------- launch ----------------
extern "C" void kernel_launch(void* const* d_in, const int* in_sizes, int n_in,
                              void* d_out, int out_size)
{
    const float* Fs    = (const float*)d_in[0];
    const float* Ff    = (const float*)d_in[1];
    const float* Wq1   = (const float*)d_in[2];
    const float* Wk1   = (const float*)d_in[3];
    const float* Wq2   = (const float*)d_in[4];
    const float* Wk2   = (const float*)d_in[5];
    const float* Wv    = (const float*)d_in[6];
    const float* Wproj = (const float*)d_in[7];
    const float* W1    = (const float*)d_in[8];
    const float* W2    = (const float*)d_in[9];
    const float* gamma = (const float*)d_in[10];
    const float* beta  = (const float*)d_in[11];
    const float* lam   = (const float*)d_in[12];
    float* out = (float*)d_out;

    prep_kernel<<<224, 256>>>(Wq1, Wk1, Wq2, Wk2, Wv, Wproj, W1, W2, lam);

    size_t proj_smem = (size_t)PROJ_SMEM_HALFS * sizeof(__half);
    cudaFuncSetAttribute(proj_kernel, cudaFuncAttributeMaxDynamicSharedMemorySize, (int)proj_smem);
    proj_kernel<<<dim3(32, Bsz), 256, proj_smem>>>(Fs, Ff);

    size_t flash_smem = (size_t)FLASH_SMEM_HALFS * sizeof(__half);
    cudaFuncSetAttribute(flash_kernel, cudaFuncAttributeMaxDynamicSharedMemorySize, (int)flash_smem);
    flash_kernel<<<dim3(32, Bsz), 256, flash_smem>>>();

    size_t ffn_smem = (size_t)FFN_SMEM_HALFS * sizeof(__half);
    cudaFuncSetAttribute(ffn_kernel, cudaFuncAttributeMaxDynamicSharedMemorySize, (int)ffn_smem);
    ffn_kernel<<<dim3(32, Bsz), 256, ffn_smem>>>();

    bnapply_kernel<<<(Bsz*Cc*Nn)/256, 256>>>(gamma, beta, out);
}

// round 6
// speedup vs baseline: 13.6168x; 1.1140x over previous
#include <cuda_runtime.h>
#include <cuda_fp16.h>
#include <math.h>
#include <stdint.h>

// Problem constants
#define Bsz 4
#define Cc  64
#define Nn  4096
#define HIDD 256
#define EPSBN 1e-5f
#define LOG2E 1.44269504088896340736f

// ---------------- scratch (__device__ globals; no allocation) ----------------
__device__ float  gFl [Bsz*Cc*Nn];     // Fs+Ff, channel-major (fp32, exact residual)
__device__ __half gQ  [Bsz*Nn*128];    // [0.125*log2e*q1 | -0.125*lam*log2e*q2], token-major
__device__ __half gK  [Bsz*Nn*128];    // [k1 | k2], token-major
__device__ __half gVT [Bsz*Cc*Nn];     // v, d-major [B][D][N]
__device__ float  gY  [Bsz*Cc*Nn];     // FFN output, channel-major
__device__ float  gBNsum[2*Cc];        // per-channel sum / sumsq accumulators

// fp16 weight caches (filled by prep kernel each launch)
__device__ __half gWqk[5*4096];        // q1,k1,q2,k2,v  (scales folded into q1,q2)
__device__ __half gWp [4096];
__device__ __half gW1h[HIDD*Cc];
__device__ __half gW2h[Cc*HIDD];

// ---------------- mma / ldmatrix / math helpers ----------------
__device__ __forceinline__ void mma_f16(float* c, const uint32_t* a, uint32_t b0, uint32_t b1) {
    asm volatile(
        "mma.sync.aligned.m16n8k16.row.col.f32.f16.f16.f32 "
        "{%0,%1,%2,%3}, {%4,%5,%6,%7}, {%8,%9}, {%0,%1,%2,%3};"
        : "+f"(c[0]), "+f"(c[1]), "+f"(c[2]), "+f"(c[3])
        : "r"(a[0]), "r"(a[1]), "r"(a[2]), "r"(a[3]), "r"(b0), "r"(b1));
}

__device__ __forceinline__ void ldsm_x4(uint32_t* r, const __half* p) {
    uint32_t addr = (uint32_t)__cvta_generic_to_shared(p);
    asm volatile("ldmatrix.sync.aligned.m8n8.x4.shared.b16 {%0,%1,%2,%3}, [%4];"
        : "=r"(r[0]), "=r"(r[1]), "=r"(r[2]), "=r"(r[3]) : "r"(addr));
}

__device__ __forceinline__ uint32_t pack2(float x, float y) {
    __half2 h = __floats2half2_rn(x, y);
    return *(uint32_t*)&h;
}

__device__ __forceinline__ float ex2(float x) {
    float r; asm("ex2.approx.f32 %0, %1;" : "=f"(r) : "f"(x)); return r;
}

// packed fp16x2 exp2 — P entries are <=1 and feed fp16 MMA anyway
__device__ __forceinline__ uint32_t h2ex2(float x, float y) {
    uint32_t p = pack2(x, y), r;
    asm("ex2.approx.f16x2 %0, %1;" : "=r"(r) : "r"(p));
    return r;
}

__device__ __forceinline__ void cp16(void* s, const void* g) {
    uint32_t sa = (uint32_t)__cvta_generic_to_shared(s);
    asm volatile("cp.async.cg.shared.global [%0], [%1], 16;" :: "r"(sa), "l"(g));
}

// ---------------- K0: weight prep + BN acc zero ----------------
__global__ void prep_kernel(const float* __restrict__ Wq1, const float* __restrict__ Wk1,
                            const float* __restrict__ Wq2, const float* __restrict__ Wk2,
                            const float* __restrict__ Wv,  const float* __restrict__ Wproj,
                            const float* __restrict__ W1,  const float* __restrict__ W2,
                            const float* __restrict__ lam_p)
{
    int idx = blockIdx.x * blockDim.x + threadIdx.x;
    if (idx < 128) gBNsum[idx] = 0.f;
    if (idx < 20480) {
        int m = idx >> 12, r = idx & 4095;
        const float* src[5] = {Wq1, Wk1, Wq2, Wk2, Wv};
        float scl = (m == 0) ? 0.125f*LOG2E : (m == 2) ? -0.125f*LOG2E * __ldg(lam_p) : 1.0f;
        gWqk[idx] = __float2half(src[m][r] * scl);
    } else if (idx < 24576) {
        gWp[idx - 20480] = __float2half(Wproj[idx - 20480]);
    } else if (idx < 40960) {
        gW1h[idx - 24576] = __float2half(W1[idx - 24576]);
    } else {
        gW2h[idx - 40960] = __float2half(W2[idx - 40960]);
    }
}

// ---------------- K1: fused add + 5 input projections ----------------
#define XS_LD 66
#define WS_LD 72
#define PROJ_SMEM_HALFS (128*XS_LD + 320*WS_LD)

__global__ void __launch_bounds__(256) proj_kernel(
    const float* __restrict__ Fs, const float* __restrict__ Ff)
{
    extern __shared__ __half sh[];
    __half* xs = sh;
    __half* ws = sh + 128*XS_LD;

    int b  = blockIdx.y;
    int n0 = blockIdx.x << 7;
    int t  = threadIdx.x;
    int w = t >> 5, lane = t & 31, g = lane >> 2, t4 = lane & 3;
    int lrow = lane & 7, lcol = (lane >> 3) * 8;

    for (int idx = t; idx < 8192; idx += 256) {
        int c = idx >> 7, n = idx & 127;
        size_t gi = (size_t)((b<<6) + c)*Nn + n0 + n;
        float v = Fs[gi] + Ff[gi];
        gFl[gi] = v;
        xs[n*XS_LD + c] = __float2half(v);
    }
    for (int idx = t; idx < 2560; idx += 256) {
        int r = idx >> 3, ch = idx & 7;
        *(uint4*)&ws[r*WS_LD + ch*8] = ((const uint4*)gWqk)[r*8 + ch];
    }
    __syncthreads();

    int row0 = w*16 + g;

    uint32_t xa[4][4];
    #pragma unroll
    for (int ks = 0; ks < 4; ks++) {
        xa[ks][0] = *(uint32_t*)&xs[ row0     *XS_LD + 16*ks + 2*t4];
        xa[ks][1] = *(uint32_t*)&xs[(row0 + 8)*XS_LD + 16*ks + 2*t4];
        xa[ks][2] = *(uint32_t*)&xs[ row0     *XS_LD + 16*ks + 2*t4 + 8];
        xa[ks][3] = *(uint32_t*)&xs[(row0 + 8)*XS_LD + 16*ks + 2*t4 + 8];
    }

    for (int m = 0; m < 5; m++) {
        float acc[8][4];
        #pragma unroll
        for (int nt = 0; nt < 8; nt++)
            acc[nt][0] = acc[nt][1] = acc[nt][2] = acc[nt][3] = 0.f;

        #pragma unroll
        for (int nt = 0; nt < 8; nt++) {
            const __half* wb = ws + (m*64 + nt*8 + lrow)*WS_LD + lcol;
            #pragma unroll
            for (int ks2 = 0; ks2 < 2; ks2++) {
                uint32_t bb[4];
                ldsm_x4(bb, wb + 32*ks2);
                mma_f16(acc[nt], xa[2*ks2],     bb[0], bb[1]);
                mma_f16(acc[nt], xa[2*ks2 + 1], bb[2], bb[3]);
            }
        }

        if (m == 4) {
            #pragma unroll
            for (int nt = 0; nt < 8; nt++) {
                int d0 = nt*8 + 2*t4;
                gVT[((b<<6) + d0    )*Nn + n0 + row0    ] = __float2half(acc[nt][0]);
                gVT[((b<<6) + d0 + 1)*Nn + n0 + row0    ] = __float2half(acc[nt][1]);
                gVT[((b<<6) + d0    )*Nn + n0 + row0 + 8] = __float2half(acc[nt][2]);
                gVT[((b<<6) + d0 + 1)*Nn + n0 + row0 + 8] = __float2half(acc[nt][3]);
            }
        } else {
            __half* dst = (m == 0 || m == 2) ? gQ : gK;
            int off = (m >= 2) ? 64 : 0;
            #pragma unroll
            for (int nt = 0; nt < 8; nt++) {
                *(uint32_t*)&dst[(size_t)(b*Nn + n0 + row0    )*128 + off + nt*8 + 2*t4]
                    = pack2(acc[nt][0], acc[nt][1]);
                *(uint32_t*)&dst[(size_t)(b*Nn + n0 + row0 + 8)*128 + off + nt*8 + 2*t4]
                    = pack2(acc[nt][2], acc[nt][3]);
            }
        }
    }
}

// ---------------- K2: flash attention + Wproj + FFN + BN partials, all fused ----------------
#define KS_LD 136
#define VT_LD 72
#define WP_LD 72
#define W1_LD 72
#define W2_LD 264
#define YS_LD 132
#define KBUF (64*KS_LD)
#define VBUF (72*VT_LD)            // rows 64..71: ones row (64) + zero rows
#define SM_WP  (2*KBUF + 2*VBUF)
#define SM_W1  (SM_WP + 64*WP_LD)
#define SM_W2  (SM_W1 + HIDD*W1_LD)
#define FLASH_SMEM_HALFS (SM_W2 + 64*W2_LD)

__global__ void __launch_bounds__(256) flash_kernel()
{
    extern __shared__ __half sh[];
    __half* ks  = sh;
    __half* vs  = sh + 2*KBUF;
    __half* wp  = sh + SM_WP;
    __half* w1s = sh + SM_W1;
    __half* w2s = sh + SM_W2;

    int b  = blockIdx.y;
    int q0 = blockIdx.x << 7;
    int t  = threadIdx.x;
    int w = t >> 5, lane = t & 31, g = lane >> 2, t4 = lane & 3;
    int row0 = w*16 + g, row1 = row0 + 8;
    int lrow = lane & 7, lcol = (lane >> 3) * 8;

    // stage weights (fp16 uint4 copies from caches)
    for (int idx = t; idx < 512; idx += 256) {
        int c = idx >> 3, ch = idx & 7;
        *(uint4*)&wp[c*WP_LD + ch*8] = ((const uint4*)gWp)[c*8 + ch];
    }
    for (int idx = t; idx < 2048; idx += 256) {
        int e = idx >> 3, ch = idx & 7;
        *(uint4*)&w1s[e*W1_LD + ch*8] = ((const uint4*)gW1h)[e*8 + ch];
    }
    for (int idx = t; idx < 2048; idx += 256) {
        int c = idx >> 5, ch = idx & 31;
        *(uint4*)&w2s[c*W2_LD + ch*8] = ((const uint4*)gW2h)[c*32 + ch];
    }
    // V-buffer constant rows: row 64 = ones (row-sum column), rows 65..71 = 0
    for (int idx = t; idx < 8*VT_LD; idx += 256) {
        int r = idx / VT_LD;
        __half v = (r == 0) ? __float2half(1.f) : __float2half(0.f);
        vs[64*VT_LD + idx]        = v;
        vs[VBUF + 64*VT_LD + idx] = v;
    }
    // stage Q tile through ks region
    const uint4* Qg = (const uint4*)(gQ + (size_t)(b*Nn + q0)*128);
    for (int idx = t; idx < 2048; idx += 256) {
        int r = idx >> 4, ch = idx & 15;
        *(uint4*)&ks[r*KS_LD + ch*8] = Qg[r*16 + ch];
    }
    __syncthreads();

    uint32_t qa[8][4];
    #pragma unroll
    for (int kst = 0; kst < 8; kst++) {
        qa[kst][0] = *(uint32_t*)&ks[row0*KS_LD + 16*kst + 2*t4];
        qa[kst][1] = *(uint32_t*)&ks[row1*KS_LD + 16*kst + 2*t4];
        qa[kst][2] = *(uint32_t*)&ks[row0*KS_LD + 16*kst + 2*t4 + 8];
        qa[kst][3] = *(uint32_t*)&ks[row1*KS_LD + 16*kst + 2*t4 + 8];
    }
    __syncthreads();

    // 9 output groups: 0..7 = attention dims, 8 = row-sum column (l)
    float oc[9][4];
    #pragma unroll
    for (int nt = 0; nt < 9; nt++)
        oc[nt][0] = oc[nt][1] = oc[nt][2] = oc[nt][3] = 0.f;
    float m0 = -1e30f, m1 = -1e30f;

    const uint4* Kg = (const uint4*)(gK  + (size_t)b*Nn*128);
    const uint4* Vg = (const uint4*)(gVT + (size_t)b*64*Nn);

    {   // prefetch tile 0
        for (int idx = t; idx < 1024; idx += 256) {
            int r = idx >> 4, ch = idx & 15;
            cp16(&ks[r*KS_LD + ch*8], &Kg[r*16 + ch]);
        }
        for (int idx = t; idx < 512; idx += 256) {
            int d = idx >> 3, ch = idx & 7;
            cp16(&vs[d*VT_LD + ch*8], &Vg[d*512 + ch]);
        }
        asm volatile("cp.async.commit_group;");
    }

    for (int kt = 0; kt < 64; kt++) {
        __half* kc = ks + (kt & 1)*KBUF;
        __half* vc = vs + (kt & 1)*VBUF;

        if (kt + 1 < 64) {
            __half* kd = ks + ((kt + 1) & 1)*KBUF;
            __half* vd = vs + ((kt + 1) & 1)*VBUF;
            int kt0 = (kt + 1) << 6;
            for (int idx = t; idx < 1024; idx += 256) {
                int r = idx >> 4, ch = idx & 15;
                cp16(&kd[r*KS_LD + ch*8], &Kg[(kt0 + r)*16 + ch]);
            }
            for (int idx = t; idx < 512; idx += 256) {
                int d = idx >> 3, ch = idx & 7;
                cp16(&vd[d*VT_LD + ch*8], &Vg[d*512 + (kt0 >> 3) + ch]);
            }
            asm volatile("cp.async.commit_group;");
            asm volatile("cp.async.wait_group 1;");
        } else {
            asm volatile("cp.async.wait_group 0;");
        }
        __syncthreads();

        // ---- S = Q K^T ----
        float sc[8][4];
        #pragma unroll
        for (int nt = 0; nt < 8; nt++) {
            sc[nt][0] = sc[nt][1] = sc[nt][2] = sc[nt][3] = 0.f;
            const __half* kb = &kc[(nt*8 + lrow)*KS_LD + lcol];
            #pragma unroll
            for (int kst2 = 0; kst2 < 4; kst2++) {
                uint32_t bb[4];
                ldsm_x4(bb, kb + 32*kst2);
                mma_f16(sc[nt], qa[2*kst2],     bb[0], bb[1]);
                mma_f16(sc[nt], qa[2*kst2 + 1], bb[2], bb[3]);
            }
        }

        // ---- online softmax: P directly in fp16x2; l via ones-column MMA ----
        float mx0 = -1e30f, mx1 = -1e30f;
        #pragma unroll
        for (int nt = 0; nt < 8; nt++) {
            mx0 = fmaxf(mx0, fmaxf(sc[nt][0], sc[nt][1]));
            mx1 = fmaxf(mx1, fmaxf(sc[nt][2], sc[nt][3]));
        }
        mx0 = fmaxf(mx0, __shfl_xor_sync(0xffffffffu, mx0, 1));
        mx0 = fmaxf(mx0, __shfl_xor_sync(0xffffffffu, mx0, 2));
        mx1 = fmaxf(mx1, __shfl_xor_sync(0xffffffffu, mx1, 1));
        mx1 = fmaxf(mx1, __shfl_xor_sync(0xffffffffu, mx1, 2));

        float mn0 = fmaxf(m0, mx0), mn1 = fmaxf(m1, mx1);
        float cr0 = ex2(m0 - mn0), cr1 = ex2(m1 - mn1);
        m0 = mn0; m1 = mn1;

        uint32_t pa[4][4];
        #pragma unroll
        for (int kst = 0; kst < 4; kst++) {
            pa[kst][0] = h2ex2(sc[2*kst  ][0] - mn0, sc[2*kst  ][1] - mn0);
            pa[kst][1] = h2ex2(sc[2*kst  ][2] - mn1, sc[2*kst  ][3] - mn1);
            pa[kst][2] = h2ex2(sc[2*kst+1][0] - mn0, sc[2*kst+1][1] - mn0);
            pa[kst][3] = h2ex2(sc[2*kst+1][2] - mn1, sc[2*kst+1][3] - mn1);
        }
        #pragma unroll
        for (int nt = 0; nt < 9; nt++) {
            oc[nt][0] *= cr0; oc[nt][1] *= cr0;
            oc[nt][2] *= cr1; oc[nt][3] *= cr1;
        }

        // ---- O(+l) += P V : 9 n-tiles ----
        #pragma unroll
        for (int nt = 0; nt < 9; nt++) {
            const __half* vb = &vc[(nt*8 + lrow)*VT_LD + lcol];
            #pragma unroll
            for (int kst2 = 0; kst2 < 2; kst2++) {
                uint32_t bb[4];
                ldsm_x4(bb, vb + 32*kst2);
                mma_f16(oc[nt], pa[2*kst2],     bb[0], bb[1]);
                mma_f16(oc[nt], pa[2*kst2 + 1], bb[2], bb[3]);
            }
        }
        __syncthreads();
    }

    // ---- l lives in column 64 (t4==0 lanes, c[0]/c[2]) ----
    float l0 = __shfl_sync(0xffffffffu, oc[8][0], lane & 28);
    float l1 = __shfl_sync(0xffffffffu, oc[8][2], lane & 28);
    float inv0 = 1.f / l0, inv1 = 1.f / l1;

    // ---- output projection: po = (O/l) @ Wproj^T ----
    uint32_t oa[4][4];
    #pragma unroll
    for (int kst = 0; kst < 4; kst++) {
        oa[kst][0] = pack2(oc[2*kst  ][0]*inv0, oc[2*kst  ][1]*inv0);
        oa[kst][1] = pack2(oc[2*kst  ][2]*inv1, oc[2*kst  ][3]*inv1);
        oa[kst][2] = pack2(oc[2*kst+1][0]*inv0, oc[2*kst+1][1]*inv0);
        oa[kst][3] = pack2(oc[2*kst+1][2]*inv1, oc[2*kst+1][3]*inv1);
    }
    float po[8][4];
    #pragma unroll
    for (int nt = 0; nt < 8; nt++) {
        po[nt][0] = po[nt][1] = po[nt][2] = po[nt][3] = 0.f;
        const __half* wb = &wp[(nt*8 + lrow)*WP_LD + lcol];
        #pragma unroll
        for (int kst2 = 0; kst2 < 2; kst2++) {
            uint32_t bb[4];
            ldsm_x4(bb, wb + 32*kst2);
            mma_f16(po[nt], oa[2*kst2],     bb[0], bb[1]);
            mma_f16(po[nt], oa[2*kst2 + 1], bb[2], bb[3]);
        }
    }

    // ---- FFN: fa (A-frags) directly from po C-frags ----
    uint32_t fa[4][4];
    #pragma unroll
    for (int ks = 0; ks < 4; ks++) {
        fa[ks][0] = pack2(po[2*ks  ][0], po[2*ks  ][1]);
        fa[ks][1] = pack2(po[2*ks  ][2], po[2*ks  ][3]);
        fa[ks][2] = pack2(po[2*ks+1][0], po[2*ks+1][1]);
        fa[ks][3] = pack2(po[2*ks+1][2], po[2*ks+1][3]);
    }

    float yacc[8][4];
    #pragma unroll
    for (int nt = 0; nt < 8; nt++)
        yacc[nt][0] = yacc[nt][1] = yacc[nt][2] = yacc[nt][3] = 0.f;

    for (int ch = 0; ch < 4; ch++) {
        float hacc[8][4];
        #pragma unroll
        for (int nt = 0; nt < 8; nt++) {
            hacc[nt][0] = hacc[nt][1] = hacc[nt][2] = hacc[nt][3] = 0.f;
            const __half* wb = &w1s[(ch*64 + nt*8 + lrow)*W1_LD + lcol];
            #pragma unroll
            for (int ks2 = 0; ks2 < 2; ks2++) {
                uint32_t bb[4];
                ldsm_x4(bb, wb + 32*ks2);
                mma_f16(hacc[nt], fa[2*ks2],     bb[0], bb[1]);
                mma_f16(hacc[nt], fa[2*ks2 + 1], bb[2], bb[3]);
            }
        }
        #pragma unroll
        for (int nt = 0; nt < 8; nt++)
            #pragma unroll
            for (int j = 0; j < 4; j++) {
                float v = hacc[nt][j];
                hacc[nt][j] = 0.5f * v * (1.f + erff(v * 0.70710678118654752f));
            }
        uint32_t ha[4][4];
        #pragma unroll
        for (int kst = 0; kst < 4; kst++) {
            ha[kst][0] = pack2(hacc[2*kst  ][0], hacc[2*kst  ][1]);
            ha[kst][1] = pack2(hacc[2*kst  ][2], hacc[2*kst  ][3]);
            ha[kst][2] = pack2(hacc[2*kst+1][0], hacc[2*kst+1][1]);
            ha[kst][3] = pack2(hacc[2*kst+1][2], hacc[2*kst+1][3]);
        }
        #pragma unroll
        for (int nt = 0; nt < 8; nt++) {
            const __half* wb = &w2s[(nt*8 + lrow)*W2_LD + ch*64 + lcol];
            #pragma unroll
            for (int kst2 = 0; kst2 < 2; kst2++) {
                uint32_t bb[4];
                ldsm_x4(bb, wb + 32*kst2);
                mma_f16(yacc[nt], ha[2*kst2],     bb[0], bb[1]);
                mma_f16(yacc[nt], ha[2*kst2 + 1], bb[2], bb[3]);
            }
        }
    }
    __syncthreads();   // all K/V smem reads done; reuse ks region as fp32 buffer

    float* ys = (float*)sh;   // [64 c][132]
    #pragma unroll
    for (int nt = 0; nt < 8; nt++) {
        int c0 = nt*8 + 2*t4;
        ys[ c0     *YS_LD + row0    ] = yacc[nt][0];
        ys[(c0 + 1)*YS_LD + row0    ] = yacc[nt][1];
        ys[ c0     *YS_LD + row0 + 8] = yacc[nt][2];
        ys[(c0 + 1)*YS_LD + row0 + 8] = yacc[nt][3];
    }
    __syncthreads();

    for (int idx = t; idx < 8192; idx += 256) {
        int c = idx >> 7, n = idx & 127;
        gY[((b<<6) + c)*Nn + q0 + n] = ys[c*YS_LD + n];
    }
    if (t < 64) {
        int c = t;
        float s = 0.f, s2 = 0.f;
        for (int j = 0; j < 128; j++) {
            int n = (j + c) & 127;
            float v = ys[c*YS_LD + n];
            s += v; s2 = fmaf(v, v, s2);
        }
        atomicAdd(&gBNsum[c], s);
        atomicAdd(&gBNsum[64 + c], s2);
    }
}

// ---------------- K3: apply BN + residual ----------------
__global__ void bnapply_kernel(const float* __restrict__ gamma,
                               const float* __restrict__ beta,
                               float* __restrict__ out)
{
    int i = blockIdx.x * blockDim.x + threadIdx.x;
    int c = (i >> 12) & 63;
    const float invN = 1.f / (Bsz * Nn);
    float mean = gBNsum[c] * invN;
    float var  = gBNsum[64 + c] * invN - mean*mean;
    float is   = rsqrtf(var + EPSBN);
    out[i] = (gY[i] - mean) * is * gamma[c] + beta[c] + gFl[i];
}

// ---------------- launch ----------------
extern "C" void kernel_launch(void* const* d_in, const int* in_sizes, int n_in,
                              void* d_out, int out_size)
{
    const float* Fs    = (const float*)d_in[0];
    const float* Ff    = (const float*)d_in[1];
    const float* Wq1   = (const float*)d_in[2];
    const float* Wk1   = (const float*)d_in[3];
    const float* Wq2   = (const float*)d_in[4];
    const float* Wk2   = (const float*)d_in[5];
    const float* Wv    = (const float*)d_in[6];
    const float* Wproj = (const float*)d_in[7];
    const float* W1    = (const float*)d_in[8];
    const float* W2    = (const float*)d_in[9];
    const float* gamma = (const float*)d_in[10];
    const float* beta  = (const float*)d_in[11];
    const float* lam   = (const float*)d_in[12];
    float* out = (float*)d_out;

    prep_kernel<<<224, 256>>>(Wq1, Wk1, Wq2, Wk2, Wv, Wproj, W1, W2, lam);

    size_t proj_smem = (size_t)PROJ_SMEM_HALFS * sizeof(__half);
    cudaFuncSetAttribute(proj_kernel, cudaFuncAttributeMaxDynamicSharedMemorySize, (int)proj_smem);
    proj_kernel<<<dim3(32, Bsz), 256, proj_smem>>>(Fs, Ff);

    size_t flash_smem = (size_t)FLASH_SMEM_HALFS * sizeof(__half);
    cudaFuncSetAttribute(flash_kernel, cudaFuncAttributeMaxDynamicSharedMemorySize, (int)flash_smem);
    flash_kernel<<<dim3(32, Bsz), 256, flash_smem>>>();

    bnapply_kernel<<<(Bsz*Cc*Nn)/256, 256>>>(gamma, beta, out);
}